// round 9
// baseline (speedup 1.0000x reference)
#include <cuda_runtime.h>
#include <cuda_fp16.h>
#include <math.h>
#include <stdint.h>

// ---------------- problem constants ----------------
#define BB    2
#define TT    2048
#define HID   4096
#define NH    32
#define NKV   8
#define HD    128
#define MROWS (BB*TT)      // 4096
#define NQ    (NH*HD)      // 4096
#define NKVD  (NKV*HD)     // 1024
#define NQKV  (NQ + 2*NKVD) // 6144
#define GROUPS (NH/NKV)    // 4

// ---------------- scratch (device globals, no allocation) ----------------
__device__ __half g_x16[(size_t)MROWS * HID];
__device__ __half g_wt[(size_t)NQKV * HID];     // concat: wq^T | wk^T | wv^T
__device__ __half g_wot[(size_t)HID * NQ];
__device__ float  g_qkv[(size_t)MROWS * NQKV];  // merged projection output
__device__ __half g_attn16[(size_t)MROWS * NQ];
__device__ __half g_q16[(size_t)MROWS * NQ];
__device__ __half g_k16[(size_t)MROWS * NKVD];
__device__ __half g_v16[(size_t)MROWS * NKVD];

// ---------------- PTX helpers (base ISA only) ----------------
__device__ __forceinline__ uint32_t smem_u32(const void* p) {
    uint32_t a;
    asm("{ .reg .u64 t; cvta.to.shared.u64 t, %1; cvt.u32.u64 %0, t; }" : "=r"(a) : "l"(p));
    return a;
}

__device__ __forceinline__ void cp16(uint32_t dst, const void* src) {
    asm volatile("cp.async.cg.shared.global [%0], [%1], 16;" :: "r"(dst), "l"(src));
}

__device__ __forceinline__ void ldsm_x4(uint32_t* r, uint32_t addr) {
    asm volatile("ldmatrix.sync.aligned.m8n8.x4.shared.b16 {%0,%1,%2,%3}, [%4];"
                 : "=r"(r[0]), "=r"(r[1]), "=r"(r[2]), "=r"(r[3]) : "r"(addr));
}

__device__ __forceinline__ void ldsm_x4_t(uint32_t* r, uint32_t addr) {
    asm volatile("ldmatrix.sync.aligned.m8n8.x4.trans.shared.b16 {%0,%1,%2,%3}, [%4];"
                 : "=r"(r[0]), "=r"(r[1]), "=r"(r[2]), "=r"(r[3]) : "r"(addr));
}

__device__ __forceinline__ void mma16816(float* d, const uint32_t* a, const uint32_t* b) {
    asm volatile(
        "mma.sync.aligned.m16n8k16.row.col.f32.f16.f16.f32 "
        "{%0,%1,%2,%3}, {%4,%5,%6,%7}, {%8,%9}, {%0,%1,%2,%3};"
        : "+f"(d[0]), "+f"(d[1]), "+f"(d[2]), "+f"(d[3])
        : "r"(a[0]), "r"(a[1]), "r"(a[2]), "r"(a[3]), "r"(b[0]), "r"(b[1]));
}

// ---------------- convert kernels ----------------
__global__ __launch_bounds__(256) void convert_f16_kernel(
    const float* __restrict__ in, __half* __restrict__ o, int n)
{
    int i = blockIdx.x * blockDim.x + threadIdx.x;
    if (i < n) o[i] = __float2half(in[i]);
}

__global__ __launch_bounds__(256) void transpose_f16_kernel(
    const float* __restrict__ in, __half* __restrict__ o, int R, int C)
{
    __shared__ float t[32][33];
    int bx = blockIdx.x * 32;   // C
    int by = blockIdx.y * 32;   // R
    int tx = threadIdx.x, ty = threadIdx.y;   // 32 x 8
#pragma unroll
    for (int j = 0; j < 32; j += 8)
        t[ty + j][tx] = in[(size_t)(by + ty + j) * C + bx + tx];
    __syncthreads();
#pragma unroll
    for (int j = 0; j < 32; j += 8)
        o[(size_t)(bx + ty + j) * R + by + tx] = __float2half(t[tx][ty + j]);
}

// extract V columns [5120,6144) of merged qkv -> fp16 [MROWS, NKVD]
__global__ __launch_bounds__(256) void extract_v_kernel(
    const float* __restrict__ qkv, __half* __restrict__ v16)
{
    int i = blockIdx.x * blockDim.x + threadIdx.x;   // over MROWS*NKVD/4
    int r = i / (NKVD / 4);
    int c = (i % (NKVD / 4)) * 4;
    float4 v = *(const float4*)&qkv[(size_t)r * NQKV + NQ + NKVD + c];
    __half2 h0 = __floats2half2_rn(v.x, v.y);
    __half2 h1 = __floats2half2_rn(v.z, v.w);
    *(__half2*)&v16[(size_t)r * NKVD + c]     = h0;
    *(__half2*)&v16[(size_t)r * NKVD + c + 2] = h1;
}

// ---------------- mma.sync single-term fp16 GEMM, 4-stage pipeline ----------------
// C[M,N] = A@B^T.  A:[M,K] fp16; B:[N,K] fp16 (pre-transposed).
// CTA 256x128, BK=64, 16 warps (4x4), warp tile 64x32.
#define GEMM_BM 256
#define GEMM_BN 128
#define GEMM_BK 64
#define GEMM_THREADS 512
#define TILE_A_BYTES (GEMM_BM * GEMM_BK * 2)   // 32 KB
#define TILE_B_BYTES (GEMM_BN * GEMM_BK * 2)   // 16 KB
#define STAGE_BYTES (TILE_A_BYTES + TILE_B_BYTES)  // 48 KB
#define NSTAGE 4
#define GEMM_SMEM (NSTAGE * STAGE_BYTES)       // 192 KB

__device__ __forceinline__ uint32_t sw_addr(uint32_t base, int row, int chunk) {
    return base + row * 128 + ((chunk ^ (row & 7)) << 4);
}

template<int ITER>
__device__ __forceinline__ void load_tileN(uint32_t sbase, const __half* g,
                                           int ld, int tid)
{
#pragma unroll
    for (int i = 0; i < ITER; i++) {
        int e = tid + i * GEMM_THREADS;
        int r = e >> 3;
        int c = e & 7;
        cp16(sw_addr(sbase, r, c), (const void*)(g + (size_t)r * ld + c * 8));
    }
}

__device__ __forceinline__ void load_stage(uint32_t st,
    const __half* gA, const __half* gB, int kk, int K, int tid)
{
    load_tileN<4>(st,                gA + kk, K, tid);
    load_tileN<2>(st + TILE_A_BYTES, gB + kk, K, tid);
}

__device__ __forceinline__ void store2(float* p, float a, float b) {
    *(float2*)p = make_float2(a, b);
}
__device__ __forceinline__ void store2(__half* p, float a, float b) {
    *(__half2*)p = __floats2half2_rn(a, b);
}

template<typename OutT>
__global__ __launch_bounds__(GEMM_THREADS, 1) void gemm_f16_kernel(
    const __half* __restrict__ A, const __half* __restrict__ B,
    OutT* __restrict__ C, int M, int N, int K)
{
    extern __shared__ char smem[];
    uint32_t sb = smem_u32(smem);
    int tid = threadIdx.x;
    int warp = tid >> 5, lane = tid & 31;
    int row0 = blockIdx.y * GEMM_BM;
    int col0 = blockIdx.x * GEMM_BN;
    int wm0 = (warp >> 2) * 64;
    int wn0 = (warp & 3) * 32;

    const __half* gA = A + (size_t)row0 * K;
    const __half* gB = B + (size_t)col0 * K;
    const int T = K / GEMM_BK;

    float acc[4][4][4];
#pragma unroll
    for (int m = 0; m < 4; m++)
#pragma unroll
        for (int n = 0; n < 4; n++)
#pragma unroll
            for (int f = 0; f < 4; f++) acc[m][n][f] = 0.f;

    // prologue: stages 0..2, one commit each
#pragma unroll
    for (int s = 0; s < 3; s++) {
        load_stage(sb + s * STAGE_BYTES, gA, gB, s * GEMM_BK, K, tid);
        asm volatile("cp.async.commit_group;" ::: "memory");
    }

    int mat = lane >> 3;
    int frow = (lane & 7) + ((mat & 1) << 3);
    int fch  = mat >> 1;

    for (int t = 0; t < T; t++) {
        // prefetch t+3 (slot reuse safe: trailing barrier of iter t-1 passed)
        if (t + 3 < T)
            load_stage(sb + ((t + 3) & 3) * STAGE_BYTES, gA, gB, (t + 3) * GEMM_BK, K, tid);
        asm volatile("cp.async.commit_group;" ::: "memory");   // always (may be empty)
        asm volatile("cp.async.wait_group 3;" ::: "memory");   // stage t ready
        __syncthreads();

        uint32_t st = sb + (t & 3) * STAGE_BYTES;
        uint32_t sA = st, sB = st + TILE_A_BYTES;

#pragma unroll
        for (int ks = 0; ks < 4; ks++) {
            int kc = ks * 2 + fch;
            uint32_t bf[2][4];
#pragma unroll
            for (int g = 0; g < 2; g++) {
                int brow = wn0 + g * 16 + frow;
                ldsm_x4(bf[g], sw_addr(sB, brow, kc));
            }
#pragma unroll
            for (int m = 0; m < 4; m++) {
                int arow = wm0 + m * 16 + frow;
                uint32_t a[4];
                ldsm_x4(a, sw_addr(sA, arow, kc));
#pragma unroll
                for (int n = 0; n < 4; n++) {
                    int g = n >> 1, h = n & 1;
                    uint32_t bff[2] = {bf[g][h], bf[g][h + 2]};
                    mma16816(acc[m][n], a, bff);
                }
            }
        }
        __syncthreads();
    }

#pragma unroll
    for (int m = 0; m < 4; m++) {
        int r0 = row0 + wm0 + m * 16 + (lane >> 2);
#pragma unroll
        for (int n = 0; n < 4; n++) {
            int c = col0 + wn0 + n * 8 + (lane & 3) * 2;
            store2(&C[(size_t)r0 * N + c],       acc[m][n][0], acc[m][n][1]);
            store2(&C[(size_t)(r0 + 8) * N + c], acc[m][n][2], acc[m][n][3]);
        }
    }
}

// ---------------- per-head RMSNorm + RoPE -> fp16 (strided input) ----------------
__global__ __launch_bounds__(128) void rmsnorm_rope_f16_kernel(
    const float* __restrict__ X, const float* __restrict__ w,
    __half* __restrict__ Y, int n_heads, int ld, int base, float osc)
{
    int row = blockIdx.x;
    int token = row / n_heads;
    int head = row % n_heads;
    int t = token % TT;
    int d = threadIdx.x;
    const float* xr = X + (size_t)token * ld + base + head * HD;

    float v = xr[d];
    float s = v * v;
#pragma unroll
    for (int off = 16; off; off >>= 1) s += __shfl_xor_sync(0xffffffffu, s, off);

    __shared__ float red[4];
    __shared__ float xs[HD];
    int warp = d >> 5, lane = d & 31;
    if (lane == 0) red[warp] = s;
    __syncthreads();
    float tot = red[0] + red[1] + red[2] + red[3];
    float rinv = rsqrtf(tot * (1.0f / HD) + 1e-6f);
    xs[d] = w[d] * v * rinv;
    __syncthreads();

    if (d < 64) {
        float a = xs[d];
        float b = xs[d + 64];
        double freq = pow(1.0e6, -(double)(2 * d) / 128.0);
        double ang = (double)t * freq;
        double sn, cs;
        sincos(ang, &sn, &cs);
        float fs = (float)sn, fc = (float)cs;
        __half* yr = Y + (size_t)row * HD;
        yr[d]      = __float2half((a * fc - b * fs) * osc);
        yr[d + 64] = __float2half((b * fc + a * fs) * osc);
    }
}

// ---------------- fp16 tensor-core causal GQA flash attention ----------------
// q-tile 128 (8 warps, 256 thr), k-tile 64, D=128. fp16 in/out (Q pre-scaled).
// smem: Q 32KB + 2 stages x (K 16KB + V 16KB) = 96KB.
#define FL_QM 128
#define FL_SMEM (FL_QM * 256 + 4 * 64 * 256)

__device__ __forceinline__ uint32_t fl_addr(uint32_t base, int row, int chunk) {
    return base + row * 256 + ((chunk ^ (row & 7)) << 4);
}

__device__ __forceinline__ void fl_load_kv(uint32_t sK, uint32_t sV,
    const __half* Kp, const __half* Vp, int tid)
{
#pragma unroll
    for (int i = 0; i < 4; i++) {
        int e = tid + i * 256;
        int r = e >> 4, c = e & 15;
        cp16(fl_addr(sK, r, c), Kp + (size_t)r * NKVD + c * 8);
        cp16(fl_addr(sV, r, c), Vp + (size_t)r * NKVD + c * 8);
    }
}

__global__ __launch_bounds__(256) void flash16_kernel(
    const __half* __restrict__ Q, const __half* __restrict__ Kb,
    const __half* __restrict__ Vb, __half* __restrict__ O)
{
    extern __shared__ char sm[];
    uint32_t sQ = smem_u32(sm);
    uint32_t sKV = sQ + FL_QM * 256;

    int tid = threadIdx.x, warp = tid >> 5, lane = tid & 31;
    int qt0 = blockIdx.x * FL_QM;
    int h = blockIdx.y;
    int b = blockIdx.z;
    int kvh = h / GROUPS;

    const __half* Qp = Q + ((size_t)(b * TT + qt0) * NH + h) * HD;
    const __half* Kp0 = Kb + ((size_t)b * TT * NKV + kvh) * HD;
    const __half* Vp0 = Vb + ((size_t)b * TT * NKV + kvh) * HD;

    // prologue: Q tile + KV tile 0
#pragma unroll
    for (int i = 0; i < 8; i++) {
        int e = tid + i * 256;
        int r = e >> 4, c = e & 15;
        cp16(fl_addr(sQ, r, c), Qp + (size_t)r * NQ + c * 8);
    }
    fl_load_kv(sKV, sKV + 64 * 256, Kp0, Vp0, tid);
    asm volatile("cp.async.commit_group;" ::: "memory");

    float m_lo = -1e30f, m_hi = -1e30f;
    float l_lo = 0.f, l_hi = 0.f;
    float acc[16][4];
#pragma unroll
    for (int g = 0; g < 16; g++)
#pragma unroll
        for (int f = 0; f < 4; f++) acc[g][f] = 0.f;

    int m0 = warp * 16;
    int lrow = lane & 15;
    int lch  = lane >> 4;
    int rq_lo = qt0 + m0 + (lane >> 2);   // global q row (lo half)
    int rq_hi = rq_lo + 8;
    int cbase = (lane & 3) * 2;

    int n_kt = qt0 / 64 + 2;              // covers k rows [0, qt0+128)
    for (int kt = 0; kt < n_kt; kt++) {
        int kt0 = kt * 64;
        if (kt + 1 < n_kt) {
            uint32_t st = sKV + ((kt + 1) & 1) * (2 * 64 * 256);
            fl_load_kv(st, st + 64 * 256,
                       Kp0 + (size_t)(kt + 1) * 64 * NKVD,
                       Vp0 + (size_t)(kt + 1) * 64 * NKVD, tid);
            asm volatile("cp.async.commit_group;" ::: "memory");
            asm volatile("cp.async.wait_group 1;" ::: "memory");
        } else {
            asm volatile("cp.async.wait_group 0;" ::: "memory");
        }
        __syncthreads();

        uint32_t sK = sKV + (kt & 1) * (2 * 64 * 256);
        uint32_t sV = sK + 64 * 256;

        // ---- S = Q_warp @ K^T (16 x 64) ----
        float sacc[8][4];
#pragma unroll
        for (int n = 0; n < 8; n++)
#pragma unroll
            for (int f = 0; f < 4; f++) sacc[n][f] = 0.f;

#pragma unroll
        for (int ks = 0; ks < 8; ks++) {
            uint32_t a[4];
            ldsm_x4(a, fl_addr(sQ, m0 + lrow, 2 * ks + lch));
#pragma unroll
            for (int g = 0; g < 4; g++) {
                uint32_t kf[4];
                ldsm_x4(kf, fl_addr(sK, g * 16 + lrow, 2 * ks + lch));
                uint32_t b0[2] = {kf[0], kf[2]};
                uint32_t b1[2] = {kf[1], kf[3]};
                mma16816(sacc[2 * g],     a, b0);
                mma16816(sacc[2 * g + 1], a, b1);
            }
        }

        // ---- causal mask (last two k-tiles overlap the q range) ----
        if (kt >= n_kt - 2) {
#pragma unroll
            for (int n = 0; n < 8; n++) {
                int c0 = kt0 + n * 8 + cbase, c1 = c0 + 1;
                if (c0 > rq_lo) sacc[n][0] = -1e30f;
                if (c1 > rq_lo) sacc[n][1] = -1e30f;
                if (c0 > rq_hi) sacc[n][2] = -1e30f;
                if (c1 > rq_hi) sacc[n][3] = -1e30f;
            }
        }

        // ---- online softmax (rows within warp; quad = same row) ----
        float mx_lo = -1e30f, mx_hi = -1e30f;
#pragma unroll
        for (int n = 0; n < 8; n++) {
            mx_lo = fmaxf(mx_lo, fmaxf(sacc[n][0], sacc[n][1]));
            mx_hi = fmaxf(mx_hi, fmaxf(sacc[n][2], sacc[n][3]));
        }
#pragma unroll
        for (int off = 1; off <= 2; off <<= 1) {
            mx_lo = fmaxf(mx_lo, __shfl_xor_sync(0xffffffffu, mx_lo, off));
            mx_hi = fmaxf(mx_hi, __shfl_xor_sync(0xffffffffu, mx_hi, off));
        }
        float mn_lo = fmaxf(m_lo, mx_lo);
        float mn_hi = fmaxf(m_hi, mx_hi);
        float sum_lo = 0.f, sum_hi = 0.f;
#pragma unroll
        for (int n = 0; n < 8; n++) {
            sacc[n][0] = expf(sacc[n][0] - mn_lo);
            sacc[n][1] = expf(sacc[n][1] - mn_lo);
            sacc[n][2] = expf(sacc[n][2] - mn_hi);
            sacc[n][3] = expf(sacc[n][3] - mn_hi);
            sum_lo += sacc[n][0] + sacc[n][1];
            sum_hi += sacc[n][2] + sacc[n][3];
        }
#pragma unroll
        for (int off = 1; off <= 2; off <<= 1) {
            sum_lo += __shfl_xor_sync(0xffffffffu, sum_lo, off);
            sum_hi += __shfl_xor_sync(0xffffffffu, sum_hi, off);
        }
        float al_lo = expf(m_lo - mn_lo);
        float al_hi = expf(m_hi - mn_hi);
        l_lo = l_lo * al_lo + sum_lo;  m_lo = mn_lo;
        l_hi = l_hi * al_hi + sum_hi;  m_hi = mn_hi;
#pragma unroll
        for (int g = 0; g < 16; g++) {
            acc[g][0] *= al_lo; acc[g][1] *= al_lo;
            acc[g][2] *= al_hi; acc[g][3] *= al_hi;
        }

        // ---- pack P fragments ----
        uint32_t pf[4][4];
#pragma unroll
        for (int j = 0; j < 4; j++) {
            __half2 p0 = __floats2half2_rn(sacc[2*j][0],   sacc[2*j][1]);
            __half2 p1 = __floats2half2_rn(sacc[2*j][2],   sacc[2*j][3]);
            __half2 p2 = __floats2half2_rn(sacc[2*j+1][0], sacc[2*j+1][1]);
            __half2 p3 = __floats2half2_rn(sacc[2*j+1][2], sacc[2*j+1][3]);
            pf[j][0] = *(uint32_t*)&p0;
            pf[j][1] = *(uint32_t*)&p1;
            pf[j][2] = *(uint32_t*)&p2;
            pf[j][3] = *(uint32_t*)&p3;
        }

        // ---- O += P @ V ----
        int vrow_off = (lane & 7) + ((lane >> 3) & 1) * 8;
#pragma unroll
        for (int j = 0; j < 4; j++) {
            int c0 = j * 16;
#pragma unroll
            for (int g = 0; g < 8; g++) {
                uint32_t vf[4];
                ldsm_x4_t(vf, fl_addr(sV, c0 + vrow_off, 2 * g + lch));
                uint32_t b0[2] = {vf[0], vf[1]};
                uint32_t b1[2] = {vf[2], vf[3]};
                mma16816(acc[2 * g],     pf[j], b0);
                mma16816(acc[2 * g + 1], pf[j], b1);
            }
        }
        __syncthreads();
    }

    // ---- epilogue: fp16 output ----
    float inv_lo = 1.f / l_lo, inv_hi = 1.f / l_hi;
    size_t base_lo = (size_t)(b * TT + rq_lo) * NQ + h * HD;
    size_t base_hi = (size_t)(b * TT + rq_hi) * NQ + h * HD;
#pragma unroll
    for (int g = 0; g < 16; g++) {
        int d = g * 8 + cbase;
        *(__half2*)&O[base_lo + d] = __floats2half2_rn(acc[g][0] * inv_lo, acc[g][1] * inv_lo);
        *(__half2*)&O[base_hi + d] = __floats2half2_rn(acc[g][2] * inv_hi, acc[g][3] * inv_hi);
    }
}

// ---------------- launch ----------------
extern "C" void kernel_launch(void* const* d_in, const int* in_sizes, int n_in,
                              void* d_out, int out_size)
{
    const float* x   = (const float*)d_in[0];
    const float* wq  = (const float*)d_in[1];
    const float* wk  = (const float*)d_in[2];
    const float* wv  = (const float*)d_in[3];
    const float* wo  = (const float*)d_in[4];
    const float* qnw = (const float*)d_in[5];
    const float* knw = (const float*)d_in[6];
    float* out = (float*)d_out;

    __half *x16, *wt, *wot, *a16, *q16, *k16, *v16;
    float *qkv;
    cudaGetSymbolAddress((void**)&x16, g_x16);
    cudaGetSymbolAddress((void**)&wt, g_wt);
    cudaGetSymbolAddress((void**)&wot, g_wot);
    cudaGetSymbolAddress((void**)&a16, g_attn16);
    cudaGetSymbolAddress((void**)&qkv, g_qkv);
    cudaGetSymbolAddress((void**)&q16, g_q16);
    cudaGetSymbolAddress((void**)&k16, g_k16);
    cudaGetSymbolAddress((void**)&v16, g_v16);

    // convert x to fp16, transpose weights into concat buffer + wo
    convert_f16_kernel<<<(MROWS * HID + 255) / 256, 256>>>(x, x16, MROWS * HID);
    transpose_f16_kernel<<<dim3(NQ / 32, HID / 32), dim3(32, 8)>>>(wq, wt, HID, NQ);
    transpose_f16_kernel<<<dim3(NKVD / 32, HID / 32), dim3(32, 8)>>>(
        wk, wt + (size_t)NQ * HID, HID, NKVD);
    transpose_f16_kernel<<<dim3(NKVD / 32, HID / 32), dim3(32, 8)>>>(
        wv, wt + (size_t)(NQ + NKVD) * HID, HID, NKVD);
    transpose_f16_kernel<<<dim3(HID / 32, NQ / 32), dim3(32, 8)>>>(wo, wot, NQ, HID);

    cudaFuncSetAttribute(gemm_f16_kernel<float>,
                         cudaFuncAttributeMaxDynamicSharedMemorySize, GEMM_SMEM);

    // merged QKV projection: [4096, 4096] @ [4096, 6144]
    gemm_f16_kernel<float><<<dim3(NQKV / GEMM_BN, MROWS / GEMM_BM), GEMM_THREADS, GEMM_SMEM>>>(
        x16, wt, qkv, MROWS, NQKV, HID);

    // extract V (fp16), rmsnorm+rope Q/K (fp16, Q pre-scaled)
    extract_v_kernel<<<(MROWS * NKVD / 4 + 255) / 256, 256>>>(qkv, v16);
    rmsnorm_rope_f16_kernel<<<MROWS * NH, 128>>>(qkv, qnw, q16, NH, NQKV, 0,
                                                 0.08838834764831845f);
    rmsnorm_rope_f16_kernel<<<MROWS * NKV, 128>>>(qkv, knw, k16, NKV, NQKV, NQ, 1.0f);

    // flash attention (q-tile 128)
    cudaFuncSetAttribute(flash16_kernel, cudaFuncAttributeMaxDynamicSharedMemorySize, FL_SMEM);
    flash16_kernel<<<dim3(TT / FL_QM, NH, BB), 256, FL_SMEM>>>(q16, k16, v16, a16);

    // output projection
    gemm_f16_kernel<float><<<dim3(HID / GEMM_BN, MROWS / GEMM_BM), GEMM_THREADS, GEMM_SMEM>>>(
        a16, wot, out, MROWS, HID, NQ);
}

// round 10
// speedup vs baseline: 1.0418x; 1.0418x over previous
#include <cuda_runtime.h>
#include <cuda_fp16.h>
#include <math.h>
#include <stdint.h>

// ---------------- problem constants ----------------
#define BB    2
#define TT    2048
#define HID   4096
#define NH    32
#define NKV   8
#define HD    128
#define MROWS (BB*TT)      // 4096
#define NQ    (NH*HD)      // 4096
#define NKVD  (NKV*HD)     // 1024
#define NQKV  (NQ + 2*NKVD) // 6144
#define GROUPS (NH/NKV)    // 4

// ---------------- scratch (device globals, no allocation) ----------------
__device__ __half g_x16[(size_t)MROWS * HID];
__device__ __half g_wt[(size_t)NQKV * HID];     // concat: wq^T | wk^T | wv^T
__device__ __half g_wot[(size_t)HID * NQ];
__device__ float  g_qkv[(size_t)MROWS * NQKV];  // merged projection output
__device__ __half g_attn16[(size_t)MROWS * NQ];
__device__ __half g_q16[(size_t)MROWS * NQ];
__device__ __half g_k16[(size_t)MROWS * NKVD];
__device__ __half g_v16[(size_t)MROWS * NKVD];

// ---------------- PTX helpers (base ISA only) ----------------
__device__ __forceinline__ uint32_t smem_u32(const void* p) {
    uint32_t a;
    asm("{ .reg .u64 t; cvta.to.shared.u64 t, %1; cvt.u32.u64 %0, t; }" : "=r"(a) : "l"(p));
    return a;
}

__device__ __forceinline__ void cp16(uint32_t dst, const void* src) {
    asm volatile("cp.async.cg.shared.global [%0], [%1], 16;" :: "r"(dst), "l"(src));
}

__device__ __forceinline__ void ldsm_x4(uint32_t* r, uint32_t addr) {
    asm volatile("ldmatrix.sync.aligned.m8n8.x4.shared.b16 {%0,%1,%2,%3}, [%4];"
                 : "=r"(r[0]), "=r"(r[1]), "=r"(r[2]), "=r"(r[3]) : "r"(addr));
}

__device__ __forceinline__ void ldsm_x4_t(uint32_t* r, uint32_t addr) {
    asm volatile("ldmatrix.sync.aligned.m8n8.x4.trans.shared.b16 {%0,%1,%2,%3}, [%4];"
                 : "=r"(r[0]), "=r"(r[1]), "=r"(r[2]), "=r"(r[3]) : "r"(addr));
}

__device__ __forceinline__ void mma16816(float* d, const uint32_t* a, const uint32_t* b) {
    asm volatile(
        "mma.sync.aligned.m16n8k16.row.col.f32.f16.f16.f32 "
        "{%0,%1,%2,%3}, {%4,%5,%6,%7}, {%8,%9}, {%0,%1,%2,%3};"
        : "+f"(d[0]), "+f"(d[1]), "+f"(d[2]), "+f"(d[3])
        : "r"(a[0]), "r"(a[1]), "r"(a[2]), "r"(a[3]), "r"(b[0]), "r"(b[1]));
}

// ---------------- convert kernels ----------------
__global__ __launch_bounds__(256) void convert_f16_kernel(
    const float* __restrict__ in, __half* __restrict__ o, int n)
{
    int i = blockIdx.x * blockDim.x + threadIdx.x;
    if (i < n) o[i] = __float2half(in[i]);
}

__global__ __launch_bounds__(256) void transpose_f16_kernel(
    const float* __restrict__ in, __half* __restrict__ o, int R, int C)
{
    __shared__ float t[32][33];
    int bx = blockIdx.x * 32;   // C
    int by = blockIdx.y * 32;   // R
    int tx = threadIdx.x, ty = threadIdx.y;   // 32 x 8
#pragma unroll
    for (int j = 0; j < 32; j += 8)
        t[ty + j][tx] = in[(size_t)(by + ty + j) * C + bx + tx];
    __syncthreads();
#pragma unroll
    for (int j = 0; j < 32; j += 8)
        o[(size_t)(bx + ty + j) * R + by + tx] = __float2half(t[tx][ty + j]);
}

// transpose wk and wv in ONE launch (z selects source)
__global__ __launch_bounds__(256) void transpose_kv_kernel(
    const float* __restrict__ wk, const float* __restrict__ wv,
    __half* __restrict__ wt)
{
    __shared__ float t[32][33];
    const float* in = blockIdx.z ? wv : wk;
    __half* o = wt + (size_t)(NQ + blockIdx.z * NKVD) * HID;
    int bx = blockIdx.x * 32;   // C = NKVD
    int by = blockIdx.y * 32;   // R = HID
    int tx = threadIdx.x, ty = threadIdx.y;
#pragma unroll
    for (int j = 0; j < 32; j += 8)
        t[ty + j][tx] = in[(size_t)(by + ty + j) * NKVD + bx + tx];
    __syncthreads();
#pragma unroll
    for (int j = 0; j < 32; j += 8)
        o[(size_t)(bx + ty + j) * HID + by + tx] = __float2half(t[tx][ty + j]);
}

// extract V columns [5120,6144) of merged qkv -> fp16 [MROWS, NKVD]
__global__ __launch_bounds__(256) void extract_v_kernel(
    const float* __restrict__ qkv, __half* __restrict__ v16)
{
    int i = blockIdx.x * blockDim.x + threadIdx.x;   // over MROWS*NKVD/4
    int r = i / (NKVD / 4);
    int c = (i % (NKVD / 4)) * 4;
    float4 v = *(const float4*)&qkv[(size_t)r * NQKV + NQ + NKVD + c];
    __half2 h0 = __floats2half2_rn(v.x, v.y);
    __half2 h1 = __floats2half2_rn(v.z, v.w);
    *(__half2*)&v16[(size_t)r * NKVD + c]     = h0;
    *(__half2*)&v16[(size_t)r * NKVD + c + 2] = h1;
}

// ---------------- mma.sync single-term fp16 GEMM, 2 CTAs/SM ----------------
// C[M,N] = A@B^T.  A:[M,K] fp16; B:[N,K] fp16 (pre-transposed).
// CTA 128x128, BK=64, 8 warps (2x4), warp tile 64x32, 3-stage cp.async.
#define GEMM_BM 128
#define GEMM_BN 128
#define GEMM_BK 64
#define GEMM_THREADS 256
#define TILE_A_BYTES (GEMM_BM * GEMM_BK * 2)   // 16 KB
#define TILE_B_BYTES (GEMM_BN * GEMM_BK * 2)   // 16 KB
#define STAGE_BYTES (TILE_A_BYTES + TILE_B_BYTES)  // 32 KB
#define NSTAGE 3
#define GEMM_SMEM (NSTAGE * STAGE_BYTES)       // 96 KB -> 2 CTAs/SM

__device__ __forceinline__ uint32_t sw_addr(uint32_t base, int row, int chunk) {
    return base + row * 128 + ((chunk ^ (row & 7)) << 4);
}

template<int ITER>
__device__ __forceinline__ void load_tileN(uint32_t sbase, const __half* g,
                                           int ld, int tid)
{
#pragma unroll
    for (int i = 0; i < ITER; i++) {
        int e = tid + i * GEMM_THREADS;
        int r = e >> 3;
        int c = e & 7;
        cp16(sw_addr(sbase, r, c), (const void*)(g + (size_t)r * ld + c * 8));
    }
}

__device__ __forceinline__ void load_stage(uint32_t st,
    const __half* gA, const __half* gB, int kk, int K, int tid)
{
    load_tileN<4>(st,                gA + kk, K, tid);
    load_tileN<4>(st + TILE_A_BYTES, gB + kk, K, tid);
    asm volatile("cp.async.commit_group;" ::: "memory");
}

__device__ __forceinline__ void store2(float* p, float a, float b) {
    *(float2*)p = make_float2(a, b);
}
__device__ __forceinline__ void store2(__half* p, float a, float b) {
    *(__half2*)p = __floats2half2_rn(a, b);
}

template<typename OutT>
__global__ __launch_bounds__(GEMM_THREADS, 2) void gemm_f16_kernel(
    const __half* __restrict__ A, const __half* __restrict__ B,
    OutT* __restrict__ C, int M, int N, int K)
{
    extern __shared__ char smem[];
    uint32_t sb = smem_u32(smem);
    int tid = threadIdx.x;
    int warp = tid >> 5, lane = tid & 31;
    int row0 = blockIdx.y * GEMM_BM;
    int col0 = blockIdx.x * GEMM_BN;
    int wm0 = (warp >> 2) * 64;        // 0 or 64
    int wn0 = (warp & 3) * 32;         // 0..96

    const __half* gA = A + (size_t)row0 * K;
    const __half* gB = B + (size_t)col0 * K;
    const int T = K / GEMM_BK;

    float acc[4][4][4];
#pragma unroll
    for (int m = 0; m < 4; m++)
#pragma unroll
        for (int n = 0; n < 4; n++)
#pragma unroll
            for (int f = 0; f < 4; f++) acc[m][n][f] = 0.f;

    // prologue: stages 0,1
    load_stage(sb,               gA, gB, 0,       K, tid);
    load_stage(sb + STAGE_BYTES, gA, gB, GEMM_BK, K, tid);

    int mat = lane >> 3;
    int frow = (lane & 7) + ((mat & 1) << 3);
    int fch  = mat >> 1;

    for (int t = 0; t < T; t++) {
        // stage t ready when <=1 newer group outstanding (0 on last iter)
        if (t == T - 1) asm volatile("cp.async.wait_group 0;" ::: "memory");
        else            asm volatile("cp.async.wait_group 1;" ::: "memory");
        __syncthreads();   // also: all warps finished iter t-1 -> slot (t+2)%3 reusable

        // prefetch AFTER the sync (slot (t+2)%3 == slot (t-1)%3 now safe)
        if (t + 2 < T)
            load_stage(sb + ((t + 2) % NSTAGE) * STAGE_BYTES, gA, gB,
                       (t + 2) * GEMM_BK, K, tid);

        uint32_t st = sb + (t % NSTAGE) * STAGE_BYTES;
        uint32_t sA = st, sB = st + TILE_A_BYTES;

#pragma unroll
        for (int ks = 0; ks < 4; ks++) {
            int kc = ks * 2 + fch;
            uint32_t bf[2][4];
#pragma unroll
            for (int g = 0; g < 2; g++) {
                int brow = wn0 + g * 16 + frow;
                ldsm_x4(bf[g], sw_addr(sB, brow, kc));
            }
#pragma unroll
            for (int m = 0; m < 4; m++) {
                int arow = wm0 + m * 16 + frow;
                uint32_t a[4];
                ldsm_x4(a, sw_addr(sA, arow, kc));
#pragma unroll
                for (int n = 0; n < 4; n++) {
                    int g = n >> 1, h = n & 1;
                    uint32_t bff[2] = {bf[g][h], bf[g][h + 2]};
                    mma16816(acc[m][n], a, bff);
                }
            }
        }
        // no trailing sync: next iteration's leading sync provides the barrier
    }

#pragma unroll
    for (int m = 0; m < 4; m++) {
        int r0 = row0 + wm0 + m * 16 + (lane >> 2);
#pragma unroll
        for (int n = 0; n < 4; n++) {
            int c = col0 + wn0 + n * 8 + (lane & 3) * 2;
            store2(&C[(size_t)r0 * N + c],       acc[m][n][0], acc[m][n][1]);
            store2(&C[(size_t)(r0 + 8) * N + c], acc[m][n][2], acc[m][n][3]);
        }
    }
}

// ---------------- per-head RMSNorm + RoPE -> fp16 (strided input) ----------------
__global__ __launch_bounds__(128) void rmsnorm_rope_f16_kernel(
    const float* __restrict__ X, const float* __restrict__ w,
    __half* __restrict__ Y, int n_heads, int ld, int base, float osc)
{
    int row = blockIdx.x;
    int token = row / n_heads;
    int head = row % n_heads;
    int t = token % TT;
    int d = threadIdx.x;
    const float* xr = X + (size_t)token * ld + base + head * HD;

    float v = xr[d];
    float s = v * v;
#pragma unroll
    for (int off = 16; off; off >>= 1) s += __shfl_xor_sync(0xffffffffu, s, off);

    __shared__ float red[4];
    __shared__ float xs[HD];
    int warp = d >> 5, lane = d & 31;
    if (lane == 0) red[warp] = s;
    __syncthreads();
    float tot = red[0] + red[1] + red[2] + red[3];
    float rinv = rsqrtf(tot * (1.0f / HD) + 1e-6f);
    xs[d] = w[d] * v * rinv;
    __syncthreads();

    if (d < 64) {
        float a = xs[d];
        float b = xs[d + 64];
        double freq = pow(1.0e6, -(double)(2 * d) / 128.0);
        double ang = (double)t * freq;
        double sn, cs;
        sincos(ang, &sn, &cs);
        float fs = (float)sn, fc = (float)cs;
        __half* yr = Y + (size_t)row * HD;
        yr[d]      = __float2half((a * fc - b * fs) * osc);
        yr[d + 64] = __float2half((b * fc + a * fs) * osc);
    }
}

// ---------------- fp16 tensor-core causal GQA flash attention ----------------
// q-tile 128 (8 warps, 256 thr), k-tile 64, D=128. fp16 in/out (Q pre-scaled).
#define FL_QM 128
#define FL_SMEM (FL_QM * 256 + 4 * 64 * 256)

__device__ __forceinline__ uint32_t fl_addr(uint32_t base, int row, int chunk) {
    return base + row * 256 + ((chunk ^ (row & 7)) << 4);
}

__device__ __forceinline__ void fl_load_kv(uint32_t sK, uint32_t sV,
    const __half* Kp, const __half* Vp, int tid)
{
#pragma unroll
    for (int i = 0; i < 4; i++) {
        int e = tid + i * 256;
        int r = e >> 4, c = e & 15;
        cp16(fl_addr(sK, r, c), Kp + (size_t)r * NKVD + c * 8);
        cp16(fl_addr(sV, r, c), Vp + (size_t)r * NKVD + c * 8);
    }
}

__global__ __launch_bounds__(256) void flash16_kernel(
    const __half* __restrict__ Q, const __half* __restrict__ Kb,
    const __half* __restrict__ Vb, __half* __restrict__ O)
{
    extern __shared__ char sm[];
    uint32_t sQ = smem_u32(sm);
    uint32_t sKV = sQ + FL_QM * 256;

    int tid = threadIdx.x, warp = tid >> 5, lane = tid & 31;
    int qt0 = blockIdx.x * FL_QM;
    int h = blockIdx.y;
    int b = blockIdx.z;
    int kvh = h / GROUPS;

    const __half* Qp = Q + ((size_t)(b * TT + qt0) * NH + h) * HD;
    const __half* Kp0 = Kb + ((size_t)b * TT * NKV + kvh) * HD;
    const __half* Vp0 = Vb + ((size_t)b * TT * NKV + kvh) * HD;

#pragma unroll
    for (int i = 0; i < 8; i++) {
        int e = tid + i * 256;
        int r = e >> 4, c = e & 15;
        cp16(fl_addr(sQ, r, c), Qp + (size_t)r * NQ + c * 8);
    }
    fl_load_kv(sKV, sKV + 64 * 256, Kp0, Vp0, tid);
    asm volatile("cp.async.commit_group;" ::: "memory");

    float m_lo = -1e30f, m_hi = -1e30f;
    float l_lo = 0.f, l_hi = 0.f;
    float acc[16][4];
#pragma unroll
    for (int g = 0; g < 16; g++)
#pragma unroll
        for (int f = 0; f < 4; f++) acc[g][f] = 0.f;

    int m0 = warp * 16;
    int lrow = lane & 15;
    int lch  = lane >> 4;
    int rq_lo = qt0 + m0 + (lane >> 2);
    int rq_hi = rq_lo + 8;
    int cbase = (lane & 3) * 2;

    int n_kt = qt0 / 64 + 2;
    for (int kt = 0; kt < n_kt; kt++) {
        int kt0 = kt * 64;
        if (kt + 1 < n_kt) {
            uint32_t st = sKV + ((kt + 1) & 1) * (2 * 64 * 256);
            fl_load_kv(st, st + 64 * 256,
                       Kp0 + (size_t)(kt + 1) * 64 * NKVD,
                       Vp0 + (size_t)(kt + 1) * 64 * NKVD, tid);
            asm volatile("cp.async.commit_group;" ::: "memory");
            asm volatile("cp.async.wait_group 1;" ::: "memory");
        } else {
            asm volatile("cp.async.wait_group 0;" ::: "memory");
        }
        __syncthreads();

        uint32_t sK = sKV + (kt & 1) * (2 * 64 * 256);
        uint32_t sV = sK + 64 * 256;

        // ---- S = Q_warp @ K^T ----
        float sacc[8][4];
#pragma unroll
        for (int n = 0; n < 8; n++)
#pragma unroll
            for (int f = 0; f < 4; f++) sacc[n][f] = 0.f;

#pragma unroll
        for (int ks = 0; ks < 8; ks++) {
            uint32_t a[4];
            ldsm_x4(a, fl_addr(sQ, m0 + lrow, 2 * ks + lch));
#pragma unroll
            for (int g = 0; g < 4; g++) {
                uint32_t kf[4];
                ldsm_x4(kf, fl_addr(sK, g * 16 + lrow, 2 * ks + lch));
                uint32_t b0[2] = {kf[0], kf[2]};
                uint32_t b1[2] = {kf[1], kf[3]};
                mma16816(sacc[2 * g],     a, b0);
                mma16816(sacc[2 * g + 1], a, b1);
            }
        }

        // ---- causal mask ----
        if (kt >= n_kt - 2) {
#pragma unroll
            for (int n = 0; n < 8; n++) {
                int c0 = kt0 + n * 8 + cbase, c1 = c0 + 1;
                if (c0 > rq_lo) sacc[n][0] = -1e30f;
                if (c1 > rq_lo) sacc[n][1] = -1e30f;
                if (c0 > rq_hi) sacc[n][2] = -1e30f;
                if (c1 > rq_hi) sacc[n][3] = -1e30f;
            }
        }

        // ---- online softmax ----
        float mx_lo = -1e30f, mx_hi = -1e30f;
#pragma unroll
        for (int n = 0; n < 8; n++) {
            mx_lo = fmaxf(mx_lo, fmaxf(sacc[n][0], sacc[n][1]));
            mx_hi = fmaxf(mx_hi, fmaxf(sacc[n][2], sacc[n][3]));
        }
#pragma unroll
        for (int off = 1; off <= 2; off <<= 1) {
            mx_lo = fmaxf(mx_lo, __shfl_xor_sync(0xffffffffu, mx_lo, off));
            mx_hi = fmaxf(mx_hi, __shfl_xor_sync(0xffffffffu, mx_hi, off));
        }
        float mn_lo = fmaxf(m_lo, mx_lo);
        float mn_hi = fmaxf(m_hi, mx_hi);
        float sum_lo = 0.f, sum_hi = 0.f;
#pragma unroll
        for (int n = 0; n < 8; n++) {
            sacc[n][0] = expf(sacc[n][0] - mn_lo);
            sacc[n][1] = expf(sacc[n][1] - mn_lo);
            sacc[n][2] = expf(sacc[n][2] - mn_hi);
            sacc[n][3] = expf(sacc[n][3] - mn_hi);
            sum_lo += sacc[n][0] + sacc[n][1];
            sum_hi += sacc[n][2] + sacc[n][3];
        }
#pragma unroll
        for (int off = 1; off <= 2; off <<= 1) {
            sum_lo += __shfl_xor_sync(0xffffffffu, sum_lo, off);
            sum_hi += __shfl_xor_sync(0xffffffffu, sum_hi, off);
        }
        float al_lo = expf(m_lo - mn_lo);
        float al_hi = expf(m_hi - mn_hi);
        l_lo = l_lo * al_lo + sum_lo;  m_lo = mn_lo;
        l_hi = l_hi * al_hi + sum_hi;  m_hi = mn_hi;
#pragma unroll
        for (int g = 0; g < 16; g++) {
            acc[g][0] *= al_lo; acc[g][1] *= al_lo;
            acc[g][2] *= al_hi; acc[g][3] *= al_hi;
        }

        // ---- pack P fragments ----
        uint32_t pf[4][4];
#pragma unroll
        for (int j = 0; j < 4; j++) {
            __half2 p0 = __floats2half2_rn(sacc[2*j][0],   sacc[2*j][1]);
            __half2 p1 = __floats2half2_rn(sacc[2*j][2],   sacc[2*j][3]);
            __half2 p2 = __floats2half2_rn(sacc[2*j+1][0], sacc[2*j+1][1]);
            __half2 p3 = __floats2half2_rn(sacc[2*j+1][2], sacc[2*j+1][3]);
            pf[j][0] = *(uint32_t*)&p0;
            pf[j][1] = *(uint32_t*)&p1;
            pf[j][2] = *(uint32_t*)&p2;
            pf[j][3] = *(uint32_t*)&p3;
        }

        // ---- O += P @ V ----
        int vrow_off = (lane & 7) + ((lane >> 3) & 1) * 8;
#pragma unroll
        for (int j = 0; j < 4; j++) {
            int c0 = j * 16;
#pragma unroll
            for (int g = 0; g < 8; g++) {
                uint32_t vf[4];
                ldsm_x4_t(vf, fl_addr(sV, c0 + vrow_off, 2 * g + lch));
                uint32_t b0[2] = {vf[0], vf[1]};
                uint32_t b1[2] = {vf[2], vf[3]};
                mma16816(acc[2 * g],     pf[j], b0);
                mma16816(acc[2 * g + 1], pf[j], b1);
            }
        }
        __syncthreads();   // protects next iteration's prefetch overwrite
    }

    // ---- epilogue: fp16 output ----
    float inv_lo = 1.f / l_lo, inv_hi = 1.f / l_hi;
    size_t base_lo = (size_t)(b * TT + rq_lo) * NQ + h * HD;
    size_t base_hi = (size_t)(b * TT + rq_hi) * NQ + h * HD;
#pragma unroll
    for (int g = 0; g < 16; g++) {
        int d = g * 8 + cbase;
        *(__half2*)&O[base_lo + d] = __floats2half2_rn(acc[g][0] * inv_lo, acc[g][1] * inv_lo);
        *(__half2*)&O[base_hi + d] = __floats2half2_rn(acc[g][2] * inv_hi, acc[g][3] * inv_hi);
    }
}

// ---------------- launch ----------------
extern "C" void kernel_launch(void* const* d_in, const int* in_sizes, int n_in,
                              void* d_out, int out_size)
{
    const float* x   = (const float*)d_in[0];
    const float* wq  = (const float*)d_in[1];
    const float* wk  = (const float*)d_in[2];
    const float* wv  = (const float*)d_in[3];
    const float* wo  = (const float*)d_in[4];
    const float* qnw = (const float*)d_in[5];
    const float* knw = (const float*)d_in[6];
    float* out = (float*)d_out;

    __half *x16, *wt, *wot, *a16, *q16, *k16, *v16;
    float *qkv;
    cudaGetSymbolAddress((void**)&x16, g_x16);
    cudaGetSymbolAddress((void**)&wt, g_wt);
    cudaGetSymbolAddress((void**)&wot, g_wot);
    cudaGetSymbolAddress((void**)&a16, g_attn16);
    cudaGetSymbolAddress((void**)&qkv, g_qkv);
    cudaGetSymbolAddress((void**)&q16, g_q16);
    cudaGetSymbolAddress((void**)&k16, g_k16);
    cudaGetSymbolAddress((void**)&v16, g_v16);

    cudaFuncSetAttribute(gemm_f16_kernel<float>,
                         cudaFuncAttributeMaxDynamicSharedMemorySize, GEMM_SMEM);
    cudaFuncSetAttribute(flash16_kernel,
                         cudaFuncAttributeMaxDynamicSharedMemorySize, FL_SMEM);

    // launch 0: x -> fp16
    convert_f16_kernel<<<(MROWS * HID + 255) / 256, 256>>>(x, x16, MROWS * HID);
    // launch 1: wq transpose
    transpose_f16_kernel<<<dim3(NQ / 32, HID / 32), dim3(32, 8)>>>(wq, wt, HID, NQ);
    // launch 2: wk + wv transpose (merged)
    transpose_kv_kernel<<<dim3(NKVD / 32, HID / 32, 2), dim3(32, 8)>>>(wk, wv, wt);
    // launch 3: merged QKV projection  <-- ncu capture slot
    gemm_f16_kernel<float><<<dim3(NQKV / GEMM_BN, MROWS / GEMM_BM), GEMM_THREADS, GEMM_SMEM>>>(
        x16, wt, qkv, MROWS, NQKV, HID);
    // launch 4: wo transpose (only needed by final GEMM)
    transpose_f16_kernel<<<dim3(HID / 32, NQ / 32), dim3(32, 8)>>>(wo, wot, NQ, HID);
    // launch 5: extract V
    extract_v_kernel<<<(MROWS * NKVD / 4 + 255) / 256, 256>>>(qkv, v16);
    // launches 6,7: rmsnorm+rope Q/K
    rmsnorm_rope_f16_kernel<<<MROWS * NH, 128>>>(qkv, qnw, q16, NH, NQKV, 0,
                                                 0.08838834764831845f);
    rmsnorm_rope_f16_kernel<<<MROWS * NKV, 128>>>(qkv, knw, k16, NKV, NQKV, NQ, 1.0f);
    // launch 8: flash attention
    flash16_kernel<<<dim3(TT / FL_QM, NH, BB), 256, FL_SMEM>>>(q16, k16, v16, a16);
    // launch 9: output projection
    gemm_f16_kernel<float><<<dim3(HID / GEMM_BN, MROWS / GEMM_BM), GEMM_THREADS, GEMM_SMEM>>>(
        a16, wot, out, MROWS, HID, NQ);
}

// round 11
// speedup vs baseline: 2.4789x; 2.3795x over previous
#include <cuda_runtime.h>
#include <cuda_fp16.h>
#include <math.h>
#include <stdint.h>

// ---------------- problem constants ----------------
#define BB    2
#define TT    2048
#define HID   4096
#define NH    32
#define NKV   8
#define HD    128
#define MROWS (BB*TT)      // 4096
#define NQ    (NH*HD)      // 4096
#define NKVD  (NKV*HD)     // 1024
#define NQKV  (NQ + 2*NKVD) // 6144
#define GROUPS (NH/NKV)    // 4

// ---------------- scratch (device globals, no allocation) ----------------
__device__ __half g_x16[(size_t)MROWS * HID];
__device__ __half g_wt[(size_t)NQKV * HID];     // concat: wq^T | wk^T | wv^T
__device__ __half g_wot[(size_t)HID * NQ];
__device__ float  g_qkv[(size_t)MROWS * NQKV];  // merged projection output
__device__ __half g_attn16[(size_t)MROWS * NQ];
__device__ __half g_q16[(size_t)MROWS * NQ];
__device__ __half g_k16[(size_t)MROWS * NKVD];
__device__ __half g_v16[(size_t)MROWS * NKVD];
__device__ float  g_cos[TT * 64];               // RoPE tables [t][d]
__device__ float  g_sin[TT * 64];

// ---------------- PTX helpers (base ISA only) ----------------
__device__ __forceinline__ uint32_t smem_u32(const void* p) {
    uint32_t a;
    asm("{ .reg .u64 t; cvta.to.shared.u64 t, %1; cvt.u32.u64 %0, t; }" : "=r"(a) : "l"(p));
    return a;
}

__device__ __forceinline__ void cp16(uint32_t dst, const void* src) {
    asm volatile("cp.async.cg.shared.global [%0], [%1], 16;" :: "r"(dst), "l"(src));
}

__device__ __forceinline__ void ldsm_x4(uint32_t* r, uint32_t addr) {
    asm volatile("ldmatrix.sync.aligned.m8n8.x4.shared.b16 {%0,%1,%2,%3}, [%4];"
                 : "=r"(r[0]), "=r"(r[1]), "=r"(r[2]), "=r"(r[3]) : "r"(addr));
}

__device__ __forceinline__ void ldsm_x4_t(uint32_t* r, uint32_t addr) {
    asm volatile("ldmatrix.sync.aligned.m8n8.x4.trans.shared.b16 {%0,%1,%2,%3}, [%4];"
                 : "=r"(r[0]), "=r"(r[1]), "=r"(r[2]), "=r"(r[3]) : "r"(addr));
}

__device__ __forceinline__ void mma16816(float* d, const uint32_t* a, const uint32_t* b) {
    asm volatile(
        "mma.sync.aligned.m16n8k16.row.col.f32.f16.f16.f32 "
        "{%0,%1,%2,%3}, {%4,%5,%6,%7}, {%8,%9}, {%0,%1,%2,%3};"
        : "+f"(d[0]), "+f"(d[1]), "+f"(d[2]), "+f"(d[3])
        : "r"(a[0]), "r"(a[1]), "r"(a[2]), "r"(a[3]), "r"(b[0]), "r"(b[1]));
}

// ---------------- RoPE table precompute (one-time, fp64 isolated here) ----------------
// Stores EXACTLY the float values the hot kernels previously computed inline.
__global__ __launch_bounds__(256) void rope_table_kernel(
    float* __restrict__ ctab, float* __restrict__ stab)
{
    int i = blockIdx.x * blockDim.x + threadIdx.x;   // t*64 + d
    if (i >= TT * 64) return;
    int t = i >> 6, d = i & 63;
    double freq = pow(1.0e6, -(double)(2 * d) / 128.0);
    double ang = (double)t * freq;
    double sn, cs;
    sincos(ang, &sn, &cs);
    ctab[i] = (float)cs;
    stab[i] = (float)sn;
}

// ---------------- convert kernels ----------------
__global__ __launch_bounds__(256) void convert_f16_kernel(
    const float* __restrict__ in, __half* __restrict__ o, int n)
{
    int i = blockIdx.x * blockDim.x + threadIdx.x;
    if (i < n) o[i] = __float2half(in[i]);
}

__global__ __launch_bounds__(256) void transpose_f16_kernel(
    const float* __restrict__ in, __half* __restrict__ o, int R, int C)
{
    __shared__ float t[32][33];
    int bx = blockIdx.x * 32;   // C
    int by = blockIdx.y * 32;   // R
    int tx = threadIdx.x, ty = threadIdx.y;   // 32 x 8
#pragma unroll
    for (int j = 0; j < 32; j += 8)
        t[ty + j][tx] = in[(size_t)(by + ty + j) * C + bx + tx];
    __syncthreads();
#pragma unroll
    for (int j = 0; j < 32; j += 8)
        o[(size_t)(bx + ty + j) * R + by + tx] = __float2half(t[tx][ty + j]);
}

// transpose wk and wv in ONE launch (z selects source)
__global__ __launch_bounds__(256) void transpose_kv_kernel(
    const float* __restrict__ wk, const float* __restrict__ wv,
    __half* __restrict__ wt)
{
    __shared__ float t[32][33];
    const float* in = blockIdx.z ? wv : wk;
    __half* o = wt + (size_t)(NQ + blockIdx.z * NKVD) * HID;
    int bx = blockIdx.x * 32;
    int by = blockIdx.y * 32;
    int tx = threadIdx.x, ty = threadIdx.y;
#pragma unroll
    for (int j = 0; j < 32; j += 8)
        t[ty + j][tx] = in[(size_t)(by + ty + j) * NKVD + bx + tx];
    __syncthreads();
#pragma unroll
    for (int j = 0; j < 32; j += 8)
        o[(size_t)(bx + ty + j) * HID + by + tx] = __float2half(t[tx][ty + j]);
}

// extract V columns [5120,6144) of merged qkv -> fp16 [MROWS, NKVD]
__global__ __launch_bounds__(256) void extract_v_kernel(
    const float* __restrict__ qkv, __half* __restrict__ v16)
{
    int i = blockIdx.x * blockDim.x + threadIdx.x;
    int r = i / (NKVD / 4);
    int c = (i % (NKVD / 4)) * 4;
    float4 v = *(const float4*)&qkv[(size_t)r * NQKV + NQ + NKVD + c];
    __half2 h0 = __floats2half2_rn(v.x, v.y);
    __half2 h1 = __floats2half2_rn(v.z, v.w);
    *(__half2*)&v16[(size_t)r * NKVD + c]     = h0;
    *(__half2*)&v16[(size_t)r * NKVD + c + 2] = h1;
}

// ---------------- mma.sync single-term fp16 GEMM, 2 CTAs/SM ----------------
#define GEMM_BM 128
#define GEMM_BN 128
#define GEMM_BK 64
#define GEMM_THREADS 256
#define TILE_A_BYTES (GEMM_BM * GEMM_BK * 2)   // 16 KB
#define TILE_B_BYTES (GEMM_BN * GEMM_BK * 2)   // 16 KB
#define STAGE_BYTES (TILE_A_BYTES + TILE_B_BYTES)  // 32 KB
#define NSTAGE 3
#define GEMM_SMEM (NSTAGE * STAGE_BYTES)       // 96 KB -> 2 CTAs/SM

__device__ __forceinline__ uint32_t sw_addr(uint32_t base, int row, int chunk) {
    return base + row * 128 + ((chunk ^ (row & 7)) << 4);
}

template<int ITER>
__device__ __forceinline__ void load_tileN(uint32_t sbase, const __half* g,
                                           int ld, int tid)
{
#pragma unroll
    for (int i = 0; i < ITER; i++) {
        int e = tid + i * GEMM_THREADS;
        int r = e >> 3;
        int c = e & 7;
        cp16(sw_addr(sbase, r, c), (const void*)(g + (size_t)r * ld + c * 8));
    }
}

__device__ __forceinline__ void load_stage(uint32_t st,
    const __half* gA, const __half* gB, int kk, int K, int tid)
{
    load_tileN<4>(st,                gA + kk, K, tid);
    load_tileN<4>(st + TILE_A_BYTES, gB + kk, K, tid);
    asm volatile("cp.async.commit_group;" ::: "memory");
}

__device__ __forceinline__ void store2(float* p, float a, float b) {
    *(float2*)p = make_float2(a, b);
}
__device__ __forceinline__ void store2(__half* p, float a, float b) {
    *(__half2*)p = __floats2half2_rn(a, b);
}

template<typename OutT>
__global__ __launch_bounds__(GEMM_THREADS, 2) void gemm_f16_kernel(
    const __half* __restrict__ A, const __half* __restrict__ B,
    OutT* __restrict__ C, int M, int N, int K)
{
    extern __shared__ char smem[];
    uint32_t sb = smem_u32(smem);
    int tid = threadIdx.x;
    int warp = tid >> 5, lane = tid & 31;
    int row0 = blockIdx.y * GEMM_BM;
    int col0 = blockIdx.x * GEMM_BN;
    int wm0 = (warp >> 2) * 64;
    int wn0 = (warp & 3) * 32;

    const __half* gA = A + (size_t)row0 * K;
    const __half* gB = B + (size_t)col0 * K;
    const int T = K / GEMM_BK;

    float acc[4][4][4];
#pragma unroll
    for (int m = 0; m < 4; m++)
#pragma unroll
        for (int n = 0; n < 4; n++)
#pragma unroll
            for (int f = 0; f < 4; f++) acc[m][n][f] = 0.f;

    load_stage(sb,               gA, gB, 0,       K, tid);
    load_stage(sb + STAGE_BYTES, gA, gB, GEMM_BK, K, tid);

    int mat = lane >> 3;
    int frow = (lane & 7) + ((mat & 1) << 3);
    int fch  = mat >> 1;

    for (int t = 0; t < T; t++) {
        if (t == T - 1) asm volatile("cp.async.wait_group 0;" ::: "memory");
        else            asm volatile("cp.async.wait_group 1;" ::: "memory");
        __syncthreads();

        if (t + 2 < T)
            load_stage(sb + ((t + 2) % NSTAGE) * STAGE_BYTES, gA, gB,
                       (t + 2) * GEMM_BK, K, tid);

        uint32_t st = sb + (t % NSTAGE) * STAGE_BYTES;
        uint32_t sA = st, sB = st + TILE_A_BYTES;

#pragma unroll
        for (int ks = 0; ks < 4; ks++) {
            int kc = ks * 2 + fch;
            uint32_t bf[2][4];
#pragma unroll
            for (int g = 0; g < 2; g++) {
                int brow = wn0 + g * 16 + frow;
                ldsm_x4(bf[g], sw_addr(sB, brow, kc));
            }
#pragma unroll
            for (int m = 0; m < 4; m++) {
                int arow = wm0 + m * 16 + frow;
                uint32_t a[4];
                ldsm_x4(a, sw_addr(sA, arow, kc));
#pragma unroll
                for (int n = 0; n < 4; n++) {
                    int g = n >> 1, h = n & 1;
                    uint32_t bff[2] = {bf[g][h], bf[g][h + 2]};
                    mma16816(acc[m][n], a, bff);
                }
            }
        }
    }

#pragma unroll
    for (int m = 0; m < 4; m++) {
        int r0 = row0 + wm0 + m * 16 + (lane >> 2);
#pragma unroll
        for (int n = 0; n < 4; n++) {
            int c = col0 + wn0 + n * 8 + (lane & 3) * 2;
            store2(&C[(size_t)r0 * N + c],       acc[m][n][0], acc[m][n][1]);
            store2(&C[(size_t)(r0 + 8) * N + c], acc[m][n][2], acc[m][n][3]);
        }
    }
}

// ---------------- per-head RMSNorm + RoPE -> fp16 (table-driven, fp32 only) ----------------
__global__ __launch_bounds__(128) void rmsnorm_rope_f16_kernel(
    const float* __restrict__ X, const float* __restrict__ w,
    const float* __restrict__ ctab, const float* __restrict__ stab,
    __half* __restrict__ Y, int n_heads, int ld, int base, float osc)
{
    int row = blockIdx.x;
    int token = row / n_heads;
    int head = row % n_heads;
    int t = token % TT;
    int d = threadIdx.x;
    const float* xr = X + (size_t)token * ld + base + head * HD;

    float v = xr[d];
    float s = v * v;
#pragma unroll
    for (int off = 16; off; off >>= 1) s += __shfl_xor_sync(0xffffffffu, s, off);

    __shared__ float red[4];
    __shared__ float xs[HD];
    int warp = d >> 5, lane = d & 31;
    if (lane == 0) red[warp] = s;
    __syncthreads();
    float tot = red[0] + red[1] + red[2] + red[3];
    float rinv = rsqrtf(tot * (1.0f / HD) + 1e-6f);
    xs[d] = w[d] * v * rinv;
    __syncthreads();

    if (d < 64) {
        float a = xs[d];
        float b = xs[d + 64];
        float fc = ctab[t * 64 + d];
        float fs = stab[t * 64 + d];
        __half* yr = Y + (size_t)row * HD;
        yr[d]      = __float2half((a * fc - b * fs) * osc);
        yr[d + 64] = __float2half((b * fc + a * fs) * osc);
    }
}

// ---------------- fp16 tensor-core causal GQA flash attention ----------------
#define FL_QM 128
#define FL_SMEM (FL_QM * 256 + 4 * 64 * 256)

__device__ __forceinline__ uint32_t fl_addr(uint32_t base, int row, int chunk) {
    return base + row * 256 + ((chunk ^ (row & 7)) << 4);
}

__device__ __forceinline__ void fl_load_kv(uint32_t sK, uint32_t sV,
    const __half* Kp, const __half* Vp, int tid)
{
#pragma unroll
    for (int i = 0; i < 4; i++) {
        int e = tid + i * 256;
        int r = e >> 4, c = e & 15;
        cp16(fl_addr(sK, r, c), Kp + (size_t)r * NKVD + c * 8);
        cp16(fl_addr(sV, r, c), Vp + (size_t)r * NKVD + c * 8);
    }
}

__global__ __launch_bounds__(256) void flash16_kernel(
    const __half* __restrict__ Q, const __half* __restrict__ Kb,
    const __half* __restrict__ Vb, __half* __restrict__ O)
{
    extern __shared__ char sm[];
    uint32_t sQ = smem_u32(sm);
    uint32_t sKV = sQ + FL_QM * 256;

    int tid = threadIdx.x, warp = tid >> 5, lane = tid & 31;
    int qt0 = blockIdx.x * FL_QM;
    int h = blockIdx.y;
    int b = blockIdx.z;
    int kvh = h / GROUPS;

    const __half* Qp = Q + ((size_t)(b * TT + qt0) * NH + h) * HD;
    const __half* Kp0 = Kb + ((size_t)b * TT * NKV + kvh) * HD;
    const __half* Vp0 = Vb + ((size_t)b * TT * NKV + kvh) * HD;

#pragma unroll
    for (int i = 0; i < 8; i++) {
        int e = tid + i * 256;
        int r = e >> 4, c = e & 15;
        cp16(fl_addr(sQ, r, c), Qp + (size_t)r * NQ + c * 8);
    }
    fl_load_kv(sKV, sKV + 64 * 256, Kp0, Vp0, tid);
    asm volatile("cp.async.commit_group;" ::: "memory");

    float m_lo = -1e30f, m_hi = -1e30f;
    float l_lo = 0.f, l_hi = 0.f;
    float acc[16][4];
#pragma unroll
    for (int g = 0; g < 16; g++)
#pragma unroll
        for (int f = 0; f < 4; f++) acc[g][f] = 0.f;

    int m0 = warp * 16;
    int lrow = lane & 15;
    int lch  = lane >> 4;
    int rq_lo = qt0 + m0 + (lane >> 2);
    int rq_hi = rq_lo + 8;
    int cbase = (lane & 3) * 2;

    int n_kt = qt0 / 64 + 2;
    for (int kt = 0; kt < n_kt; kt++) {
        int kt0 = kt * 64;
        if (kt + 1 < n_kt) {
            uint32_t st = sKV + ((kt + 1) & 1) * (2 * 64 * 256);
            fl_load_kv(st, st + 64 * 256,
                       Kp0 + (size_t)(kt + 1) * 64 * NKVD,
                       Vp0 + (size_t)(kt + 1) * 64 * NKVD, tid);
            asm volatile("cp.async.commit_group;" ::: "memory");
            asm volatile("cp.async.wait_group 1;" ::: "memory");
        } else {
            asm volatile("cp.async.wait_group 0;" ::: "memory");
        }
        __syncthreads();

        uint32_t sK = sKV + (kt & 1) * (2 * 64 * 256);
        uint32_t sV = sK + 64 * 256;

        float sacc[8][4];
#pragma unroll
        for (int n = 0; n < 8; n++)
#pragma unroll
            for (int f = 0; f < 4; f++) sacc[n][f] = 0.f;

#pragma unroll
        for (int ks = 0; ks < 8; ks++) {
            uint32_t a[4];
            ldsm_x4(a, fl_addr(sQ, m0 + lrow, 2 * ks + lch));
#pragma unroll
            for (int g = 0; g < 4; g++) {
                uint32_t kf[4];
                ldsm_x4(kf, fl_addr(sK, g * 16 + lrow, 2 * ks + lch));
                uint32_t b0[2] = {kf[0], kf[2]};
                uint32_t b1[2] = {kf[1], kf[3]};
                mma16816(sacc[2 * g],     a, b0);
                mma16816(sacc[2 * g + 1], a, b1);
            }
        }

        if (kt >= n_kt - 2) {
#pragma unroll
            for (int n = 0; n < 8; n++) {
                int c0 = kt0 + n * 8 + cbase, c1 = c0 + 1;
                if (c0 > rq_lo) sacc[n][0] = -1e30f;
                if (c1 > rq_lo) sacc[n][1] = -1e30f;
                if (c0 > rq_hi) sacc[n][2] = -1e30f;
                if (c1 > rq_hi) sacc[n][3] = -1e30f;
            }
        }

        float mx_lo = -1e30f, mx_hi = -1e30f;
#pragma unroll
        for (int n = 0; n < 8; n++) {
            mx_lo = fmaxf(mx_lo, fmaxf(sacc[n][0], sacc[n][1]));
            mx_hi = fmaxf(mx_hi, fmaxf(sacc[n][2], sacc[n][3]));
        }
#pragma unroll
        for (int off = 1; off <= 2; off <<= 1) {
            mx_lo = fmaxf(mx_lo, __shfl_xor_sync(0xffffffffu, mx_lo, off));
            mx_hi = fmaxf(mx_hi, __shfl_xor_sync(0xffffffffu, mx_hi, off));
        }
        float mn_lo = fmaxf(m_lo, mx_lo);
        float mn_hi = fmaxf(m_hi, mx_hi);
        float sum_lo = 0.f, sum_hi = 0.f;
#pragma unroll
        for (int n = 0; n < 8; n++) {
            sacc[n][0] = expf(sacc[n][0] - mn_lo);
            sacc[n][1] = expf(sacc[n][1] - mn_lo);
            sacc[n][2] = expf(sacc[n][2] - mn_hi);
            sacc[n][3] = expf(sacc[n][3] - mn_hi);
            sum_lo += sacc[n][0] + sacc[n][1];
            sum_hi += sacc[n][2] + sacc[n][3];
        }
#pragma unroll
        for (int off = 1; off <= 2; off <<= 1) {
            sum_lo += __shfl_xor_sync(0xffffffffu, sum_lo, off);
            sum_hi += __shfl_xor_sync(0xffffffffu, sum_hi, off);
        }
        float al_lo = expf(m_lo - mn_lo);
        float al_hi = expf(m_hi - mn_hi);
        l_lo = l_lo * al_lo + sum_lo;  m_lo = mn_lo;
        l_hi = l_hi * al_hi + sum_hi;  m_hi = mn_hi;
#pragma unroll
        for (int g = 0; g < 16; g++) {
            acc[g][0] *= al_lo; acc[g][1] *= al_lo;
            acc[g][2] *= al_hi; acc[g][3] *= al_hi;
        }

        uint32_t pf[4][4];
#pragma unroll
        for (int j = 0; j < 4; j++) {
            __half2 p0 = __floats2half2_rn(sacc[2*j][0],   sacc[2*j][1]);
            __half2 p1 = __floats2half2_rn(sacc[2*j][2],   sacc[2*j][3]);
            __half2 p2 = __floats2half2_rn(sacc[2*j+1][0], sacc[2*j+1][1]);
            __half2 p3 = __floats2half2_rn(sacc[2*j+1][2], sacc[2*j+1][3]);
            pf[j][0] = *(uint32_t*)&p0;
            pf[j][1] = *(uint32_t*)&p1;
            pf[j][2] = *(uint32_t*)&p2;
            pf[j][3] = *(uint32_t*)&p3;
        }

        int vrow_off = (lane & 7) + ((lane >> 3) & 1) * 8;
#pragma unroll
        for (int j = 0; j < 4; j++) {
            int c0 = j * 16;
#pragma unroll
            for (int g = 0; g < 8; g++) {
                uint32_t vf[4];
                ldsm_x4_t(vf, fl_addr(sV, c0 + vrow_off, 2 * g + lch));
                uint32_t b0[2] = {vf[0], vf[1]};
                uint32_t b1[2] = {vf[2], vf[3]};
                mma16816(acc[2 * g],     pf[j], b0);
                mma16816(acc[2 * g + 1], pf[j], b1);
            }
        }
        __syncthreads();
    }

    float inv_lo = 1.f / l_lo, inv_hi = 1.f / l_hi;
    size_t base_lo = (size_t)(b * TT + rq_lo) * NQ + h * HD;
    size_t base_hi = (size_t)(b * TT + rq_hi) * NQ + h * HD;
#pragma unroll
    for (int g = 0; g < 16; g++) {
        int d = g * 8 + cbase;
        *(__half2*)&O[base_lo + d] = __floats2half2_rn(acc[g][0] * inv_lo, acc[g][1] * inv_lo);
        *(__half2*)&O[base_hi + d] = __floats2half2_rn(acc[g][2] * inv_hi, acc[g][3] * inv_hi);
    }
}

// ---------------- launch ----------------
extern "C" void kernel_launch(void* const* d_in, const int* in_sizes, int n_in,
                              void* d_out, int out_size)
{
    const float* x   = (const float*)d_in[0];
    const float* wq  = (const float*)d_in[1];
    const float* wk  = (const float*)d_in[2];
    const float* wv  = (const float*)d_in[3];
    const float* wo  = (const float*)d_in[4];
    const float* qnw = (const float*)d_in[5];
    const float* knw = (const float*)d_in[6];
    float* out = (float*)d_out;

    __half *x16, *wt, *wot, *a16, *q16, *k16, *v16;
    float *qkv, *ctab, *stab;
    cudaGetSymbolAddress((void**)&x16, g_x16);
    cudaGetSymbolAddress((void**)&wt, g_wt);
    cudaGetSymbolAddress((void**)&wot, g_wot);
    cudaGetSymbolAddress((void**)&a16, g_attn16);
    cudaGetSymbolAddress((void**)&qkv, g_qkv);
    cudaGetSymbolAddress((void**)&q16, g_q16);
    cudaGetSymbolAddress((void**)&k16, g_k16);
    cudaGetSymbolAddress((void**)&v16, g_v16);
    cudaGetSymbolAddress((void**)&ctab, g_cos);
    cudaGetSymbolAddress((void**)&stab, g_sin);

    cudaFuncSetAttribute(gemm_f16_kernel<float>,
                         cudaFuncAttributeMaxDynamicSharedMemorySize, GEMM_SMEM);
    cudaFuncSetAttribute(flash16_kernel,
                         cudaFuncAttributeMaxDynamicSharedMemorySize, FL_SMEM);

    // launch 0: x -> fp16
    convert_f16_kernel<<<(MROWS * HID + 255) / 256, 256>>>(x, x16, MROWS * HID);
    // launch 1: wq transpose
    transpose_f16_kernel<<<dim3(NQ / 32, HID / 32), dim3(32, 8)>>>(wq, wt, HID, NQ);
    // launch 2: wk + wv transpose (merged)
    transpose_kv_kernel<<<dim3(NKVD / 32, HID / 32, 2), dim3(32, 8)>>>(wk, wv, wt);
    // launch 3: merged QKV projection  <-- ncu capture slot
    gemm_f16_kernel<float><<<dim3(NQKV / GEMM_BN, MROWS / GEMM_BM), GEMM_THREADS, GEMM_SMEM>>>(
        x16, wt, qkv, MROWS, NQKV, HID);
    // launch 4: RoPE tables (one-time fp64, off the hot path)
    rope_table_kernel<<<(TT * 64 + 255) / 256, 256>>>(ctab, stab);
    // launch 5: wo transpose
    transpose_f16_kernel<<<dim3(HID / 32, NQ / 32), dim3(32, 8)>>>(wo, wot, NQ, HID);
    // launch 6: extract V
    extract_v_kernel<<<(MROWS * NKVD / 4 + 255) / 256, 256>>>(qkv, v16);
    // launches 7,8: table-driven rmsnorm+rope Q/K
    rmsnorm_rope_f16_kernel<<<MROWS * NH, 128>>>(qkv, qnw, ctab, stab, q16, NH, NQKV, 0,
                                                 0.08838834764831845f);
    rmsnorm_rope_f16_kernel<<<MROWS * NKV, 128>>>(qkv, knw, ctab, stab, k16, NKV, NQKV, NQ, 1.0f);
    // launch 9: flash attention
    flash16_kernel<<<dim3(TT / FL_QM, NH, BB), 256, FL_SMEM>>>(q16, k16, v16, a16);
    // launch 10: output projection
    gemm_f16_kernel<float><<<dim3(HID / GEMM_BN, MROWS / GEMM_BM), GEMM_THREADS, GEMM_SMEM>>>(
        a16, wot, out, MROWS, HID, NQ);
}

// round 12
// speedup vs baseline: 2.5551x; 1.0308x over previous
#include <cuda_runtime.h>
#include <cuda_fp16.h>
#include <math.h>
#include <stdint.h>

// ---------------- problem constants ----------------
#define BB    2
#define TT    2048
#define HID   4096
#define NH    32
#define NKV   8
#define HD    128
#define MROWS (BB*TT)      // 4096
#define NQ    (NH*HD)      // 4096
#define NKVD  (NKV*HD)     // 1024
#define NQKV  (NQ + 2*NKVD) // 6144
#define GROUPS (NH/NKV)    // 4

// ---------------- scratch (device globals, no allocation) ----------------
__device__ __half g_x16[(size_t)MROWS * HID];
__device__ __half g_wt[(size_t)NQKV * HID];     // concat: wq^T | wk^T | wv^T
__device__ __half g_wot[(size_t)HID * NQ];
__device__ float  g_qkv[(size_t)MROWS * NQKV];  // merged projection output
__device__ __half g_attn16[(size_t)MROWS * NQ];
__device__ __half g_q16[(size_t)MROWS * NQ];
__device__ __half g_k16[(size_t)MROWS * NKVD];
__device__ __half g_v16[(size_t)MROWS * NKVD];
__device__ float  g_cos[TT * 64];               // RoPE tables [t][d]
__device__ float  g_sin[TT * 64];

// ---------------- PTX helpers (base ISA only) ----------------
__device__ __forceinline__ uint32_t smem_u32(const void* p) {
    uint32_t a;
    asm("{ .reg .u64 t; cvta.to.shared.u64 t, %1; cvt.u32.u64 %0, t; }" : "=r"(a) : "l"(p));
    return a;
}

__device__ __forceinline__ void cp16(uint32_t dst, const void* src) {
    asm volatile("cp.async.cg.shared.global [%0], [%1], 16;" :: "r"(dst), "l"(src));
}

__device__ __forceinline__ void ldsm_x4(uint32_t* r, uint32_t addr) {
    asm volatile("ldmatrix.sync.aligned.m8n8.x4.shared.b16 {%0,%1,%2,%3}, [%4];"
                 : "=r"(r[0]), "=r"(r[1]), "=r"(r[2]), "=r"(r[3]) : "r"(addr));
}

__device__ __forceinline__ void ldsm_x4_t(uint32_t* r, uint32_t addr) {
    asm volatile("ldmatrix.sync.aligned.m8n8.x4.trans.shared.b16 {%0,%1,%2,%3}, [%4];"
                 : "=r"(r[0]), "=r"(r[1]), "=r"(r[2]), "=r"(r[3]) : "r"(addr));
}

__device__ __forceinline__ void mma16816(float* d, const uint32_t* a, const uint32_t* b) {
    asm volatile(
        "mma.sync.aligned.m16n8k16.row.col.f32.f16.f16.f32 "
        "{%0,%1,%2,%3}, {%4,%5,%6,%7}, {%8,%9}, {%0,%1,%2,%3};"
        : "+f"(d[0]), "+f"(d[1]), "+f"(d[2]), "+f"(d[3])
        : "r"(a[0]), "r"(a[1]), "r"(a[2]), "r"(a[3]), "r"(b[0]), "r"(b[1]));
}

// ---------------- RoPE table precompute (one-time, fp64 isolated here) ----------------
__global__ __launch_bounds__(256) void rope_table_kernel(
    float* __restrict__ ctab, float* __restrict__ stab)
{
    int i = blockIdx.x * blockDim.x + threadIdx.x;   // t*64 + d
    if (i >= TT * 64) return;
    int t = i >> 6, d = i & 63;
    double freq = pow(1.0e6, -(double)(2 * d) / 128.0);
    double ang = (double)t * freq;
    double sn, cs;
    sincos(ang, &sn, &cs);
    ctab[i] = (float)cs;
    stab[i] = (float)sn;
}

// ---------------- convert kernels ----------------
__global__ __launch_bounds__(256) void convert_f16_kernel(
    const float* __restrict__ in, __half* __restrict__ o, int n)
{
    int i = blockIdx.x * blockDim.x + threadIdx.x;
    if (i < n) o[i] = __float2half(in[i]);
}

__global__ __launch_bounds__(256) void transpose_f16_kernel(
    const float* __restrict__ in, __half* __restrict__ o, int R, int C)
{
    __shared__ float t[32][33];
    int bx = blockIdx.x * 32;
    int by = blockIdx.y * 32;
    int tx = threadIdx.x, ty = threadIdx.y;
#pragma unroll
    for (int j = 0; j < 32; j += 8)
        t[ty + j][tx] = in[(size_t)(by + ty + j) * C + bx + tx];
    __syncthreads();
#pragma unroll
    for (int j = 0; j < 32; j += 8)
        o[(size_t)(bx + ty + j) * R + by + tx] = __float2half(t[tx][ty + j]);
}

// transpose wk and wv in ONE launch (z selects source)
__global__ __launch_bounds__(256) void transpose_kv_kernel(
    const float* __restrict__ wk, const float* __restrict__ wv,
    __half* __restrict__ wt)
{
    __shared__ float t[32][33];
    const float* in = blockIdx.z ? wv : wk;
    __half* o = wt + (size_t)(NQ + blockIdx.z * NKVD) * HID;
    int bx = blockIdx.x * 32;
    int by = blockIdx.y * 32;
    int tx = threadIdx.x, ty = threadIdx.y;
#pragma unroll
    for (int j = 0; j < 32; j += 8)
        t[ty + j][tx] = in[(size_t)(by + ty + j) * NKVD + bx + tx];
    __syncthreads();
#pragma unroll
    for (int j = 0; j < 32; j += 8)
        o[(size_t)(bx + ty + j) * HID + by + tx] = __float2half(t[tx][ty + j]);
}

// extract V columns [5120,6144) of merged qkv -> fp16 [MROWS, NKVD]
__global__ __launch_bounds__(256) void extract_v_kernel(
    const float* __restrict__ qkv, __half* __restrict__ v16)
{
    int i = blockIdx.x * blockDim.x + threadIdx.x;
    int r = i / (NKVD / 4);
    int c = (i % (NKVD / 4)) * 4;
    float4 v = *(const float4*)&qkv[(size_t)r * NQKV + NQ + NKVD + c];
    __half2 h0 = __floats2half2_rn(v.x, v.y);
    __half2 h1 = __floats2half2_rn(v.z, v.w);
    *(__half2*)&v16[(size_t)r * NKVD + c]     = h0;
    *(__half2*)&v16[(size_t)r * NKVD + c + 2] = h1;
}

// ---------------- mma.sync single-term fp16 GEMM, 2 CTAs/SM ----------------
#define GEMM_BM 128
#define GEMM_BN 128
#define GEMM_BK 64
#define GEMM_THREADS 256
#define TILE_A_BYTES (GEMM_BM * GEMM_BK * 2)   // 16 KB
#define TILE_B_BYTES (GEMM_BN * GEMM_BK * 2)   // 16 KB
#define STAGE_BYTES (TILE_A_BYTES + TILE_B_BYTES)  // 32 KB
#define NSTAGE 3
#define GEMM_SMEM (NSTAGE * STAGE_BYTES)       // 96 KB -> 2 CTAs/SM

__device__ __forceinline__ uint32_t sw_addr(uint32_t base, int row, int chunk) {
    return base + row * 128 + ((chunk ^ (row & 7)) << 4);
}

template<int ITER>
__device__ __forceinline__ void load_tileN(uint32_t sbase, const __half* g,
                                           int ld, int tid)
{
#pragma unroll
    for (int i = 0; i < ITER; i++) {
        int e = tid + i * GEMM_THREADS;
        int r = e >> 3;
        int c = e & 7;
        cp16(sw_addr(sbase, r, c), (const void*)(g + (size_t)r * ld + c * 8));
    }
}

__device__ __forceinline__ void load_stage(uint32_t st,
    const __half* gA, const __half* gB, int kk, int K, int tid)
{
    load_tileN<4>(st,                gA + kk, K, tid);
    load_tileN<4>(st + TILE_A_BYTES, gB + kk, K, tid);
    asm volatile("cp.async.commit_group;" ::: "memory");
}

__device__ __forceinline__ void store2(float* p, float a, float b) {
    *(float2*)p = make_float2(a, b);
}
__device__ __forceinline__ void store2(__half* p, float a, float b) {
    *(__half2*)p = __floats2half2_rn(a, b);
}

template<typename OutT>
__global__ __launch_bounds__(GEMM_THREADS, 2) void gemm_f16_kernel(
    const __half* __restrict__ A, const __half* __restrict__ B,
    OutT* __restrict__ C, int M, int N, int K)
{
    extern __shared__ char smem[];
    uint32_t sb = smem_u32(smem);
    int tid = threadIdx.x;
    int warp = tid >> 5, lane = tid & 31;
    int row0 = blockIdx.y * GEMM_BM;
    int col0 = blockIdx.x * GEMM_BN;
    int wm0 = (warp >> 2) * 64;
    int wn0 = (warp & 3) * 32;

    const __half* gA = A + (size_t)row0 * K;
    const __half* gB = B + (size_t)col0 * K;
    const int T = K / GEMM_BK;

    float acc[4][4][4];
#pragma unroll
    for (int m = 0; m < 4; m++)
#pragma unroll
        for (int n = 0; n < 4; n++)
#pragma unroll
            for (int f = 0; f < 4; f++) acc[m][n][f] = 0.f;

    load_stage(sb,               gA, gB, 0,       K, tid);
    load_stage(sb + STAGE_BYTES, gA, gB, GEMM_BK, K, tid);

    int mat = lane >> 3;
    int frow = (lane & 7) + ((mat & 1) << 3);
    int fch  = mat >> 1;

    for (int t = 0; t < T; t++) {
        if (t == T - 1) asm volatile("cp.async.wait_group 0;" ::: "memory");
        else            asm volatile("cp.async.wait_group 1;" ::: "memory");
        __syncthreads();

        bool pf = (t + 2 < T);
        uint32_t spre = sb + ((t + 2) % NSTAGE) * STAGE_BYTES;
        int kk2 = (t + 2) * GEMM_BK;

        uint32_t st = sb + (t % NSTAGE) * STAGE_BYTES;
        uint32_t sA = st, sB = st + TILE_A_BYTES;

#pragma unroll
        for (int ks = 0; ks < 4; ks++) {
            // spread prefetch: 2 cp.async per ks (A chunk ks, B chunk ks)
            if (pf) {
                int e = tid + ks * GEMM_THREADS;
                int r = e >> 3;
                int c = e & 7;
                cp16(sw_addr(spre, r, c),
                     (const void*)(gA + kk2 + (size_t)r * K + c * 8));
                cp16(sw_addr(spre + TILE_A_BYTES, r, c),
                     (const void*)(gB + kk2 + (size_t)r * K + c * 8));
            }

            int kc = ks * 2 + fch;
            uint32_t bf[2][4];
#pragma unroll
            for (int g = 0; g < 2; g++) {
                int brow = wn0 + g * 16 + frow;
                ldsm_x4(bf[g], sw_addr(sB, brow, kc));
            }
#pragma unroll
            for (int m = 0; m < 4; m++) {
                int arow = wm0 + m * 16 + frow;
                uint32_t a[4];
                ldsm_x4(a, sw_addr(sA, arow, kc));
#pragma unroll
                for (int n = 0; n < 4; n++) {
                    int g = n >> 1, h = n & 1;
                    uint32_t bff[2] = {bf[g][h], bf[g][h + 2]};
                    mma16816(acc[m][n], a, bff);
                }
            }
        }
        asm volatile("cp.async.commit_group;" ::: "memory");   // one group per t
    }

#pragma unroll
    for (int m = 0; m < 4; m++) {
        int r0 = row0 + wm0 + m * 16 + (lane >> 2);
#pragma unroll
        for (int n = 0; n < 4; n++) {
            int c = col0 + wn0 + n * 8 + (lane & 3) * 2;
            store2(&C[(size_t)r0 * N + c],       acc[m][n][0], acc[m][n][1]);
            store2(&C[(size_t)(r0 + 8) * N + c], acc[m][n][2], acc[m][n][3]);
        }
    }
}

// ---------------- per-head RMSNorm + RoPE -> fp16 (table-driven, fp32 only) ----------------
__global__ __launch_bounds__(128) void rmsnorm_rope_f16_kernel(
    const float* __restrict__ X, const float* __restrict__ w,
    const float* __restrict__ ctab, const float* __restrict__ stab,
    __half* __restrict__ Y, int n_heads, int ld, int base, float osc)
{
    int row = blockIdx.x;
    int token = row / n_heads;
    int head = row % n_heads;
    int t = token % TT;
    int d = threadIdx.x;
    const float* xr = X + (size_t)token * ld + base + head * HD;

    float v = xr[d];
    float s = v * v;
#pragma unroll
    for (int off = 16; off; off >>= 1) s += __shfl_xor_sync(0xffffffffu, s, off);

    __shared__ float red[4];
    __shared__ float xs[HD];
    int warp = d >> 5, lane = d & 31;
    if (lane == 0) red[warp] = s;
    __syncthreads();
    float tot = red[0] + red[1] + red[2] + red[3];
    float rinv = rsqrtf(tot * (1.0f / HD) + 1e-6f);
    xs[d] = w[d] * v * rinv;
    __syncthreads();

    if (d < 64) {
        float a = xs[d];
        float b = xs[d + 64];
        float fc = ctab[t * 64 + d];
        float fs = stab[t * 64 + d];
        __half* yr = Y + (size_t)row * HD;
        yr[d]      = __float2half((a * fc - b * fs) * osc);
        yr[d + 64] = __float2half((b * fc + a * fs) * osc);
    }
}

// ---------------- fp16 tensor-core causal GQA flash attention ----------------
// Q pre-scaled by log2(e)/sqrt(HD) -> softmax in base 2 (hardware EX2).
#define FL_QM 128
#define FL_SMEM (FL_QM * 256 + 4 * 64 * 256)

__device__ __forceinline__ uint32_t fl_addr(uint32_t base, int row, int chunk) {
    return base + row * 256 + ((chunk ^ (row & 7)) << 4);
}

__device__ __forceinline__ void fl_load_kv(uint32_t sK, uint32_t sV,
    const __half* Kp, const __half* Vp, int tid)
{
#pragma unroll
    for (int i = 0; i < 4; i++) {
        int e = tid + i * 256;
        int r = e >> 4, c = e & 15;
        cp16(fl_addr(sK, r, c), Kp + (size_t)r * NKVD + c * 8);
        cp16(fl_addr(sV, r, c), Vp + (size_t)r * NKVD + c * 8);
    }
}

__global__ __launch_bounds__(256) void flash16_kernel(
    const __half* __restrict__ Q, const __half* __restrict__ Kb,
    const __half* __restrict__ Vb, __half* __restrict__ O)
{
    extern __shared__ char sm[];
    uint32_t sQ = smem_u32(sm);
    uint32_t sKV = sQ + FL_QM * 256;

    int tid = threadIdx.x, warp = tid >> 5, lane = tid & 31;
    int qt0 = blockIdx.x * FL_QM;
    int h = blockIdx.y;
    int b = blockIdx.z;
    int kvh = h / GROUPS;

    const __half* Qp = Q + ((size_t)(b * TT + qt0) * NH + h) * HD;
    const __half* Kp0 = Kb + ((size_t)b * TT * NKV + kvh) * HD;
    const __half* Vp0 = Vb + ((size_t)b * TT * NKV + kvh) * HD;

#pragma unroll
    for (int i = 0; i < 8; i++) {
        int e = tid + i * 256;
        int r = e >> 4, c = e & 15;
        cp16(fl_addr(sQ, r, c), Qp + (size_t)r * NQ + c * 8);
    }
    fl_load_kv(sKV, sKV + 64 * 256, Kp0, Vp0, tid);
    asm volatile("cp.async.commit_group;" ::: "memory");

    float m_lo = -1e30f, m_hi = -1e30f;
    float l_lo = 0.f, l_hi = 0.f;
    float acc[16][4];
#pragma unroll
    for (int g = 0; g < 16; g++)
#pragma unroll
        for (int f = 0; f < 4; f++) acc[g][f] = 0.f;

    int m0 = warp * 16;
    int lrow = lane & 15;
    int lch  = lane >> 4;
    int rq_lo = qt0 + m0 + (lane >> 2);
    int rq_hi = rq_lo + 8;
    int cbase = (lane & 3) * 2;

    int n_kt = qt0 / 64 + 2;
    for (int kt = 0; kt < n_kt; kt++) {
        int kt0 = kt * 64;
        if (kt + 1 < n_kt) {
            uint32_t st = sKV + ((kt + 1) & 1) * (2 * 64 * 256);
            fl_load_kv(st, st + 64 * 256,
                       Kp0 + (size_t)(kt + 1) * 64 * NKVD,
                       Vp0 + (size_t)(kt + 1) * 64 * NKVD, tid);
            asm volatile("cp.async.commit_group;" ::: "memory");
            asm volatile("cp.async.wait_group 1;" ::: "memory");
        } else {
            asm volatile("cp.async.wait_group 0;" ::: "memory");
        }
        __syncthreads();

        uint32_t sK = sKV + (kt & 1) * (2 * 64 * 256);
        uint32_t sV = sK + 64 * 256;

        float sacc[8][4];
#pragma unroll
        for (int n = 0; n < 8; n++)
#pragma unroll
            for (int f = 0; f < 4; f++) sacc[n][f] = 0.f;

#pragma unroll
        for (int ks = 0; ks < 8; ks++) {
            uint32_t a[4];
            ldsm_x4(a, fl_addr(sQ, m0 + lrow, 2 * ks + lch));
#pragma unroll
            for (int g = 0; g < 4; g++) {
                uint32_t kf[4];
                ldsm_x4(kf, fl_addr(sK, g * 16 + lrow, 2 * ks + lch));
                uint32_t b0[2] = {kf[0], kf[2]};
                uint32_t b1[2] = {kf[1], kf[3]};
                mma16816(sacc[2 * g],     a, b0);
                mma16816(sacc[2 * g + 1], a, b1);
            }
        }

        if (kt >= n_kt - 2) {
#pragma unroll
            for (int n = 0; n < 8; n++) {
                int c0 = kt0 + n * 8 + cbase, c1 = c0 + 1;
                if (c0 > rq_lo) sacc[n][0] = -1e30f;
                if (c1 > rq_lo) sacc[n][1] = -1e30f;
                if (c0 > rq_hi) sacc[n][2] = -1e30f;
                if (c1 > rq_hi) sacc[n][3] = -1e30f;
            }
        }

        float mx_lo = -1e30f, mx_hi = -1e30f;
#pragma unroll
        for (int n = 0; n < 8; n++) {
            mx_lo = fmaxf(mx_lo, fmaxf(sacc[n][0], sacc[n][1]));
            mx_hi = fmaxf(mx_hi, fmaxf(sacc[n][2], sacc[n][3]));
        }
#pragma unroll
        for (int off = 1; off <= 2; off <<= 1) {
            mx_lo = fmaxf(mx_lo, __shfl_xor_sync(0xffffffffu, mx_lo, off));
            mx_hi = fmaxf(mx_hi, __shfl_xor_sync(0xffffffffu, mx_hi, off));
        }
        float mn_lo = fmaxf(m_lo, mx_lo);
        float mn_hi = fmaxf(m_hi, mx_hi);
        float sum_lo = 0.f, sum_hi = 0.f;
#pragma unroll
        for (int n = 0; n < 8; n++) {
            sacc[n][0] = exp2f(sacc[n][0] - mn_lo);
            sacc[n][1] = exp2f(sacc[n][1] - mn_lo);
            sacc[n][2] = exp2f(sacc[n][2] - mn_hi);
            sacc[n][3] = exp2f(sacc[n][3] - mn_hi);
            sum_lo += sacc[n][0] + sacc[n][1];
            sum_hi += sacc[n][2] + sacc[n][3];
        }
#pragma unroll
        for (int off = 1; off <= 2; off <<= 1) {
            sum_lo += __shfl_xor_sync(0xffffffffu, sum_lo, off);
            sum_hi += __shfl_xor_sync(0xffffffffu, sum_hi, off);
        }
        float al_lo = exp2f(m_lo - mn_lo);
        float al_hi = exp2f(m_hi - mn_hi);
        l_lo = l_lo * al_lo + sum_lo;  m_lo = mn_lo;
        l_hi = l_hi * al_hi + sum_hi;  m_hi = mn_hi;
#pragma unroll
        for (int g = 0; g < 16; g++) {
            acc[g][0] *= al_lo; acc[g][1] *= al_lo;
            acc[g][2] *= al_hi; acc[g][3] *= al_hi;
        }

        uint32_t pf[4][4];
#pragma unroll
        for (int j = 0; j < 4; j++) {
            __half2 p0 = __floats2half2_rn(sacc[2*j][0],   sacc[2*j][1]);
            __half2 p1 = __floats2half2_rn(sacc[2*j][2],   sacc[2*j][3]);
            __half2 p2 = __floats2half2_rn(sacc[2*j+1][0], sacc[2*j+1][1]);
            __half2 p3 = __floats2half2_rn(sacc[2*j+1][2], sacc[2*j+1][3]);
            pf[j][0] = *(uint32_t*)&p0;
            pf[j][1] = *(uint32_t*)&p1;
            pf[j][2] = *(uint32_t*)&p2;
            pf[j][3] = *(uint32_t*)&p3;
        }

        int vrow_off = (lane & 7) + ((lane >> 3) & 1) * 8;
#pragma unroll
        for (int j = 0; j < 4; j++) {
            int c0 = j * 16;
#pragma unroll
            for (int g = 0; g < 8; g++) {
                uint32_t vf[4];
                ldsm_x4_t(vf, fl_addr(sV, c0 + vrow_off, 2 * g + lch));
                uint32_t b0[2] = {vf[0], vf[1]};
                uint32_t b1[2] = {vf[2], vf[3]};
                mma16816(acc[2 * g],     pf[j], b0);
                mma16816(acc[2 * g + 1], pf[j], b1);
            }
        }
        __syncthreads();
    }

    float inv_lo = 1.f / l_lo, inv_hi = 1.f / l_hi;
    size_t base_lo = (size_t)(b * TT + rq_lo) * NQ + h * HD;
    size_t base_hi = (size_t)(b * TT + rq_hi) * NQ + h * HD;
#pragma unroll
    for (int g = 0; g < 16; g++) {
        int d = g * 8 + cbase;
        *(__half2*)&O[base_lo + d] = __floats2half2_rn(acc[g][0] * inv_lo, acc[g][1] * inv_lo);
        *(__half2*)&O[base_hi + d] = __floats2half2_rn(acc[g][2] * inv_hi, acc[g][3] * inv_hi);
    }
}

// ---------------- launch ----------------
extern "C" void kernel_launch(void* const* d_in, const int* in_sizes, int n_in,
                              void* d_out, int out_size)
{
    const float* x   = (const float*)d_in[0];
    const float* wq  = (const float*)d_in[1];
    const float* wk  = (const float*)d_in[2];
    const float* wv  = (const float*)d_in[3];
    const float* wo  = (const float*)d_in[4];
    const float* qnw = (const float*)d_in[5];
    const float* knw = (const float*)d_in[6];
    float* out = (float*)d_out;

    __half *x16, *wt, *wot, *a16, *q16, *k16, *v16;
    float *qkv, *ctab, *stab;
    cudaGetSymbolAddress((void**)&x16, g_x16);
    cudaGetSymbolAddress((void**)&wt, g_wt);
    cudaGetSymbolAddress((void**)&wot, g_wot);
    cudaGetSymbolAddress((void**)&a16, g_attn16);
    cudaGetSymbolAddress((void**)&qkv, g_qkv);
    cudaGetSymbolAddress((void**)&q16, g_q16);
    cudaGetSymbolAddress((void**)&k16, g_k16);
    cudaGetSymbolAddress((void**)&v16, g_v16);
    cudaGetSymbolAddress((void**)&ctab, g_cos);
    cudaGetSymbolAddress((void**)&stab, g_sin);

    cudaFuncSetAttribute(gemm_f16_kernel<float>,
                         cudaFuncAttributeMaxDynamicSharedMemorySize, GEMM_SMEM);
    cudaFuncSetAttribute(flash16_kernel,
                         cudaFuncAttributeMaxDynamicSharedMemorySize, FL_SMEM);

    // Q scale: 1/sqrt(HD) * log2(e)  -> base-2 softmax in flash
    const float qscale = 0.08838834764831845f * 1.4426950408889634f;

    // launch 0: x -> fp16
    convert_f16_kernel<<<(MROWS * HID + 255) / 256, 256>>>(x, x16, MROWS * HID);
    // launch 1: wq transpose
    transpose_f16_kernel<<<dim3(NQ / 32, HID / 32), dim3(32, 8)>>>(wq, wt, HID, NQ);
    // launch 2: wk + wv transpose (merged)
    transpose_kv_kernel<<<dim3(NKVD / 32, HID / 32, 2), dim3(32, 8)>>>(wk, wv, wt);
    // launch 3: merged QKV projection  <-- ncu capture slot
    gemm_f16_kernel<float><<<dim3(NQKV / GEMM_BN, MROWS / GEMM_BM), GEMM_THREADS, GEMM_SMEM>>>(
        x16, wt, qkv, MROWS, NQKV, HID);
    // launch 4: RoPE tables (one-time fp64)
    rope_table_kernel<<<(TT * 64 + 255) / 256, 256>>>(ctab, stab);
    // launch 5: wo transpose
    transpose_f16_kernel<<<dim3(HID / 32, NQ / 32), dim3(32, 8)>>>(wo, wot, NQ, HID);
    // launch 6: extract V
    extract_v_kernel<<<(MROWS * NKVD / 4 + 255) / 256, 256>>>(qkv, v16);
    // launches 7,8: table-driven rmsnorm+rope Q/K
    rmsnorm_rope_f16_kernel<<<MROWS * NH, 128>>>(qkv, qnw, ctab, stab, q16, NH, NQKV, 0, qscale);
    rmsnorm_rope_f16_kernel<<<MROWS * NKV, 128>>>(qkv, knw, ctab, stab, k16, NKV, NQKV, NQ, 1.0f);
    // launch 9: flash attention (base-2 softmax)
    flash16_kernel<<<dim3(TT / FL_QM, NH, BB), 256, FL_SMEM>>>(q16, k16, v16, a16);
    // launch 10: output projection
    gemm_f16_kernel<float><<<dim3(HID / GEMM_BN, MROWS / GEMM_BM), GEMM_THREADS, GEMM_SMEM>>>(
        a16, wot, out, MROWS, HID, NQ);
}

// round 13
// speedup vs baseline: 2.7074x; 1.0596x over previous
#include <cuda_runtime.h>
#include <cuda_fp16.h>
#include <math.h>
#include <stdint.h>

// ---------------- problem constants ----------------
#define BB    2
#define TT    2048
#define HID   4096
#define NH    32
#define NKV   8
#define HD    128
#define MROWS (BB*TT)      // 4096
#define NQ    (NH*HD)      // 4096
#define NKVD  (NKV*HD)     // 1024
#define NQKV  (NQ + 2*NKVD) // 6144
#define GROUPS (NH/NKV)    // 4

// ---------------- scratch (device globals, no allocation) ----------------
__device__ __half g_x16[(size_t)MROWS * HID];
__device__ __half g_wt[(size_t)NQKV * HID];     // concat: wq^T | wk^T | wv^T
__device__ __half g_wot[(size_t)HID * NQ];
__device__ __half g_attn16[(size_t)MROWS * NQ];
__device__ __half g_q16[(size_t)MROWS * NQ];
__device__ __half g_k16[(size_t)MROWS * NKVD];
__device__ __half g_v16[(size_t)MROWS * NKVD];
__device__ float  g_cos[TT * 64];               // RoPE tables [t][d]
__device__ float  g_sin[TT * 64];

// ---------------- PTX helpers (base ISA only) ----------------
__device__ __forceinline__ uint32_t smem_u32(const void* p) {
    uint32_t a;
    asm("{ .reg .u64 t; cvta.to.shared.u64 t, %1; cvt.u32.u64 %0, t; }" : "=r"(a) : "l"(p));
    return a;
}

__device__ __forceinline__ void cp16(uint32_t dst, const void* src) {
    asm volatile("cp.async.cg.shared.global [%0], [%1], 16;" :: "r"(dst), "l"(src));
}

__device__ __forceinline__ void ldsm_x4(uint32_t* r, uint32_t addr) {
    asm volatile("ldmatrix.sync.aligned.m8n8.x4.shared.b16 {%0,%1,%2,%3}, [%4];"
                 : "=r"(r[0]), "=r"(r[1]), "=r"(r[2]), "=r"(r[3]) : "r"(addr));
}

__device__ __forceinline__ void ldsm_x4_t(uint32_t* r, uint32_t addr) {
    asm volatile("ldmatrix.sync.aligned.m8n8.x4.trans.shared.b16 {%0,%1,%2,%3}, [%4];"
                 : "=r"(r[0]), "=r"(r[1]), "=r"(r[2]), "=r"(r[3]) : "r"(addr));
}

__device__ __forceinline__ void mma16816(float* d, const uint32_t* a, const uint32_t* b) {
    asm volatile(
        "mma.sync.aligned.m16n8k16.row.col.f32.f16.f16.f32 "
        "{%0,%1,%2,%3}, {%4,%5,%6,%7}, {%8,%9}, {%0,%1,%2,%3};"
        : "+f"(d[0]), "+f"(d[1]), "+f"(d[2]), "+f"(d[3])
        : "r"(a[0]), "r"(a[1]), "r"(a[2]), "r"(a[3]), "r"(b[0]), "r"(b[1]));
}

// ---------------- RoPE table precompute (one-time fp64) ----------------
__global__ __launch_bounds__(256) void rope_table_kernel(
    float* __restrict__ ctab, float* __restrict__ stab)
{
    int i = blockIdx.x * blockDim.x + threadIdx.x;   // t*64 + d
    if (i >= TT * 64) return;
    int t = i >> 6, d = i & 63;
    double freq = pow(1.0e6, -(double)(2 * d) / 128.0);
    double ang = (double)t * freq;
    double sn, cs;
    sincos(ang, &sn, &cs);
    ctab[i] = (float)cs;
    stab[i] = (float)sn;
}

// ---------------- convert / transpose kernels ----------------
__global__ __launch_bounds__(256) void convert_f16_kernel(
    const float* __restrict__ in, __half* __restrict__ o, int n)
{
    int i = blockIdx.x * blockDim.x + threadIdx.x;
    if (i < n) o[i] = __float2half(in[i]);
}

__global__ __launch_bounds__(256) void transpose_f16_kernel(
    const float* __restrict__ in, __half* __restrict__ o, int R, int C)
{
    __shared__ float t[32][33];
    int bx = blockIdx.x * 32;
    int by = blockIdx.y * 32;
    int tx = threadIdx.x, ty = threadIdx.y;
#pragma unroll
    for (int j = 0; j < 32; j += 8)
        t[ty + j][tx] = in[(size_t)(by + ty + j) * C + bx + tx];
    __syncthreads();
#pragma unroll
    for (int j = 0; j < 32; j += 8)
        o[(size_t)(bx + ty + j) * R + by + tx] = __float2half(t[tx][ty + j]);
}

// transpose wq / wk / wv in ONE launch (z selects source); kv blocks with bx>=32 exit
__global__ __launch_bounds__(256) void transpose_qkvw_kernel(
    const float* __restrict__ wq, const float* __restrict__ wk,
    const float* __restrict__ wv, __half* __restrict__ wt)
{
    int z = blockIdx.z;
    int C = z ? NKVD : NQ;
    if (blockIdx.x * 32 >= C) return;
    const float* in = z == 0 ? wq : (z == 1 ? wk : wv);
    __half* o = wt + (size_t)(z == 0 ? 0 : (z == 1 ? NQ : NQ + NKVD)) * HID;

    __shared__ float t[32][33];
    int bx = blockIdx.x * 32;
    int by = blockIdx.y * 32;
    int tx = threadIdx.x, ty = threadIdx.y;
#pragma unroll
    for (int j = 0; j < 32; j += 8)
        t[ty + j][tx] = in[(size_t)(by + ty + j) * C + bx + tx];
    __syncthreads();
#pragma unroll
    for (int j = 0; j < 32; j += 8)
        o[(size_t)(bx + ty + j) * HID + by + tx] = __float2half(t[tx][ty + j]);
}

// ---------------- GEMM common pieces ----------------
#define GEMM_BM 128
#define GEMM_BN 128
#define GEMM_BK 64
#define GEMM_THREADS 256
#define TILE_A_BYTES (GEMM_BM * GEMM_BK * 2)   // 16 KB
#define TILE_B_BYTES (GEMM_BN * GEMM_BK * 2)   // 16 KB
#define STAGE_BYTES (TILE_A_BYTES + TILE_B_BYTES)  // 32 KB
#define NSTAGE 3
#define GEMM_SMEM (NSTAGE * STAGE_BYTES)       // 96 KB -> 2 CTAs/SM

__device__ __forceinline__ uint32_t sw_addr(uint32_t base, int row, int chunk) {
    return base + row * 128 + ((chunk ^ (row & 7)) << 4);
}

template<int ITER>
__device__ __forceinline__ void load_tileN(uint32_t sbase, const __half* g,
                                           int ld, int tid)
{
#pragma unroll
    for (int i = 0; i < ITER; i++) {
        int e = tid + i * GEMM_THREADS;
        int r = e >> 3;
        int c = e & 7;
        cp16(sw_addr(sbase, r, c), (const void*)(g + (size_t)r * ld + c * 8));
    }
}

__device__ __forceinline__ void load_stage(uint32_t st,
    const __half* gA, const __half* gB, int kk, int K, int tid)
{
    load_tileN<4>(st,                gA + kk, K, tid);
    load_tileN<4>(st + TILE_A_BYTES, gB + kk, K, tid);
    asm volatile("cp.async.commit_group;" ::: "memory");
}

__device__ __forceinline__ void store2(float* p, float a, float b) {
    *(float2*)p = make_float2(a, b);
}
__device__ __forceinline__ void store2(__half* p, float a, float b) {
    *(__half2*)p = __floats2half2_rn(a, b);
}

// mainloop producing acc[4][4][4] (warp tile 64x32) — shared by both GEMMs
__device__ __forceinline__ void gemm_mainloop(
    uint32_t sb, const __half* gA, const __half* gB, int K, int tid,
    int warp, int lane, float acc[4][4][4])
{
    int wm0 = (warp >> 2) * 64;
    int wn0 = (warp & 3) * 32;
    const int T = K / GEMM_BK;

#pragma unroll
    for (int m = 0; m < 4; m++)
#pragma unroll
        for (int n = 0; n < 4; n++)
#pragma unroll
            for (int f = 0; f < 4; f++) acc[m][n][f] = 0.f;

    load_stage(sb,               gA, gB, 0,       K, tid);
    load_stage(sb + STAGE_BYTES, gA, gB, GEMM_BK, K, tid);

    int mat = lane >> 3;
    int frow = (lane & 7) + ((mat & 1) << 3);
    int fch  = mat >> 1;

    for (int t = 0; t < T; t++) {
        if (t == T - 1) asm volatile("cp.async.wait_group 0;" ::: "memory");
        else            asm volatile("cp.async.wait_group 1;" ::: "memory");
        __syncthreads();

        bool pf = (t + 2 < T);
        uint32_t spre = sb + ((t + 2) % NSTAGE) * STAGE_BYTES;
        int kk2 = (t + 2) * GEMM_BK;

        uint32_t st = sb + (t % NSTAGE) * STAGE_BYTES;
        uint32_t sA = st, sB = st + TILE_A_BYTES;

#pragma unroll
        for (int ks = 0; ks < 4; ks++) {
            if (pf) {
                int e = tid + ks * GEMM_THREADS;
                int r = e >> 3;
                int c = e & 7;
                cp16(sw_addr(spre, r, c),
                     (const void*)(gA + kk2 + (size_t)r * K + c * 8));
                cp16(sw_addr(spre + TILE_A_BYTES, r, c),
                     (const void*)(gB + kk2 + (size_t)r * K + c * 8));
            }

            int kc = ks * 2 + fch;
            uint32_t bf[2][4];
#pragma unroll
            for (int g = 0; g < 2; g++) {
                int brow = wn0 + g * 16 + frow;
                ldsm_x4(bf[g], sw_addr(sB, brow, kc));
            }
#pragma unroll
            for (int m = 0; m < 4; m++) {
                int arow = wm0 + m * 16 + frow;
                uint32_t a[4];
                ldsm_x4(a, sw_addr(sA, arow, kc));
#pragma unroll
                for (int n = 0; n < 4; n++) {
                    int g = n >> 1, h = n & 1;
                    uint32_t bff[2] = {bf[g][h], bf[g][h + 2]};
                    mma16816(acc[m][n], a, bff);
                }
            }
        }
        asm volatile("cp.async.commit_group;" ::: "memory");
    }
}

// ---------------- generic fp16 GEMM (wo projection) ----------------
template<typename OutT>
__global__ __launch_bounds__(GEMM_THREADS, 2) void gemm_f16_kernel(
    const __half* __restrict__ A, const __half* __restrict__ B,
    OutT* __restrict__ C, int M, int N, int K)
{
    extern __shared__ char smem[];
    uint32_t sb = smem_u32(smem);
    int tid = threadIdx.x;
    int warp = tid >> 5, lane = tid & 31;
    int row0 = blockIdx.y * GEMM_BM;
    int col0 = blockIdx.x * GEMM_BN;
    int wm0 = (warp >> 2) * 64;
    int wn0 = (warp & 3) * 32;

    float acc[4][4][4];
    gemm_mainloop(sb, A + (size_t)row0 * K, B + (size_t)col0 * K, K, tid, warp, lane, acc);

#pragma unroll
    for (int m = 0; m < 4; m++) {
        int r0 = row0 + wm0 + m * 16 + (lane >> 2);
#pragma unroll
        for (int n = 0; n < 4; n++) {
            int c = col0 + wn0 + n * 8 + (lane & 3) * 2;
            store2(&C[(size_t)r0 * N + c],       acc[m][n][0], acc[m][n][1]);
            store2(&C[(size_t)(r0 + 8) * N + c], acc[m][n][2], acc[m][n][3]);
        }
    }
}

// ---------------- QKV GEMM with fused RMSNorm + RoPE / V-convert epilogue ----------------
// Tile cols = exactly one 128-dim head. Q: cols [0,4096) -> q16 (rope, qscale);
// K: [4096,5120) -> k16 (rope); V: [5120,6144) -> v16 (plain fp16).
#define XS_PITCH 132

__global__ __launch_bounds__(GEMM_THREADS, 2) void gemm_qkv_kernel(
    const __half* __restrict__ A, const __half* __restrict__ B,
    const float* __restrict__ qnw, const float* __restrict__ knw,
    const float* __restrict__ ctab, const float* __restrict__ stab,
    __half* __restrict__ Q, __half* __restrict__ Ko, __half* __restrict__ V,
    float qscale)
{
    extern __shared__ char smem[];
    uint32_t sb = smem_u32(smem);
    int tid = threadIdx.x;
    int warp = tid >> 5, lane = tid & 31;
    int row0 = blockIdx.y * GEMM_BM;
    int col0 = blockIdx.x * GEMM_BN;
    int wm0 = (warp >> 2) * 64;
    int wn0 = (warp & 3) * 32;

    float acc[4][4][4];
    gemm_mainloop(sb, A + (size_t)row0 * HID, B + (size_t)col0 * HID, HID,
                  tid, warp, lane, acc);
    __syncthreads();   // mainloop smem reads done before epilogue reuse

    int q2 = lane >> 2;          // 0..7 row-in-16 group
    int cq = (lane & 3) * 2;     // col pair base within n8

    // ---- V region: plain fp16 convert ----
    if (col0 >= NQ + NKVD) {
        int cb = col0 - NQ - NKVD;
#pragma unroll
        for (int m = 0; m < 4; m++) {
            int r0 = row0 + wm0 + m * 16 + q2;
#pragma unroll
            for (int n = 0; n < 4; n++) {
                int c = cb + wn0 + n * 8 + cq;
                store2(&V[(size_t)r0 * NKVD + c],       acc[m][n][0], acc[m][n][1]);
                store2(&V[(size_t)(r0 + 8) * NKVD + c], acc[m][n][2], acc[m][n][3]);
            }
        }
        return;
    }

    // ---- Q/K region: RMSNorm + RoPE ----
    bool isQ = (col0 < NQ);
    const float* w = isQ ? qnw : knw;
    float osc = isQ ? qscale : 1.0f;

    float* xs  = (float*)smem;                     // [128][XS_PITCH] = 67.6 KB
    float* red = xs + 128 * XS_PITCH;              // [128][4] = 2 KB

    // per-thread row partial sums of x^2
    float p_lo[4], p_hi[4];
#pragma unroll
    for (int m = 0; m < 4; m++) {
        float sl = 0.f, sh = 0.f;
#pragma unroll
        for (int n = 0; n < 4; n++) {
            sl += acc[m][n][0] * acc[m][n][0] + acc[m][n][1] * acc[m][n][1];
            sh += acc[m][n][2] * acc[m][n][2] + acc[m][n][3] * acc[m][n][3];
        }
        p_lo[m] = sl; p_hi[m] = sh;
    }
#pragma unroll
    for (int off = 1; off <= 2; off <<= 1) {
#pragma unroll
        for (int m = 0; m < 4; m++) {
            p_lo[m] += __shfl_xor_sync(0xffffffffu, p_lo[m], off);
            p_hi[m] += __shfl_xor_sync(0xffffffffu, p_hi[m], off);
        }
    }
    int wn_idx = warp & 3;
    if ((lane & 3) == 0) {
#pragma unroll
        for (int m = 0; m < 4; m++) {
            int r = wm0 + m * 16 + q2;
            red[r * 4 + wn_idx]       = p_lo[m];
            red[(r + 8) * 4 + wn_idx] = p_hi[m];
        }
    }
    __syncthreads();

    // normalize + weight -> xs
#pragma unroll
    for (int m = 0; m < 4; m++) {
        int r_lo = wm0 + m * 16 + q2;
        int r_hi = r_lo + 8;
        float tl = red[r_lo * 4] + red[r_lo * 4 + 1] + red[r_lo * 4 + 2] + red[r_lo * 4 + 3];
        float th = red[r_hi * 4] + red[r_hi * 4 + 1] + red[r_hi * 4 + 2] + red[r_hi * 4 + 3];
        float ril = rsqrtf(tl * (1.0f / HD) + 1e-6f);
        float rih = rsqrtf(th * (1.0f / HD) + 1e-6f);
#pragma unroll
        for (int n = 0; n < 4; n++) {
            int d0 = wn0 + n * 8 + cq;
            float w0 = w[d0], w1 = w[d0 + 1];
            xs[r_lo * XS_PITCH + d0]     = acc[m][n][0] * w0 * ril;
            xs[r_lo * XS_PITCH + d0 + 1] = acc[m][n][1] * w1 * ril;
            xs[r_hi * XS_PITCH + d0]     = acc[m][n][2] * w0 * rih;
            xs[r_hi * XS_PITCH + d0 + 1] = acc[m][n][3] * w1 * rih;
        }
    }
    __syncthreads();

    // rope + fp16 store
    __half* out = isQ ? Q : Ko;
    int ld = isQ ? NQ : NKVD;
    int cb = isQ ? col0 : col0 - NQ;
#pragma unroll
    for (int i = 0; i < 32; i++) {
        int idx = tid + i * GEMM_THREADS;    // 8192 (r, d<64) pairs
        int r = idx >> 6, d = idx & 63;
        float a = xs[r * XS_PITCH + d];
        float b = xs[r * XS_PITCH + d + 64];
        int t = (row0 + r) & (TT - 1);
        float fc = ctab[t * 64 + d];
        float fs = stab[t * 64 + d];
        size_t o = (size_t)(row0 + r) * ld + cb;
        out[o + d]      = __float2half((a * fc - b * fs) * osc);
        out[o + d + 64] = __float2half((b * fc + a * fs) * osc);
    }
}

// ---------------- fp16 tensor-core causal GQA flash attention ----------------
// Q pre-scaled by log2(e)/sqrt(HD) (folded in GEMM epilogue) -> base-2 softmax.
// LPT: longest q-tiles (largest qt0) scheduled first.
#define FL_QM 128
#define FL_SMEM (FL_QM * 256 + 4 * 64 * 256)

__device__ __forceinline__ uint32_t fl_addr(uint32_t base, int row, int chunk) {
    return base + row * 256 + ((chunk ^ (row & 7)) << 4);
}

__device__ __forceinline__ void fl_load_kv(uint32_t sK, uint32_t sV,
    const __half* Kp, const __half* Vp, int tid)
{
#pragma unroll
    for (int i = 0; i < 4; i++) {
        int e = tid + i * 256;
        int r = e >> 4, c = e & 15;
        cp16(fl_addr(sK, r, c), Kp + (size_t)r * NKVD + c * 8);
        cp16(fl_addr(sV, r, c), Vp + (size_t)r * NKVD + c * 8);
    }
}

__global__ __launch_bounds__(256) void flash16_kernel(
    const __half* __restrict__ Q, const __half* __restrict__ Kb,
    const __half* __restrict__ Vb, __half* __restrict__ O)
{
    extern __shared__ char sm[];
    uint32_t sQ = smem_u32(sm);
    uint32_t sKV = sQ + FL_QM * 256;

    int tid = threadIdx.x, warp = tid >> 5, lane = tid & 31;
    int qt0 = (TT / FL_QM - 1 - blockIdx.x) * FL_QM;   // LPT: big tiles first
    int h = blockIdx.y;
    int b = blockIdx.z;
    int kvh = h / GROUPS;

    const __half* Qp = Q + ((size_t)(b * TT + qt0) * NH + h) * HD;
    const __half* Kp0 = Kb + ((size_t)b * TT * NKV + kvh) * HD;
    const __half* Vp0 = Vb + ((size_t)b * TT * NKV + kvh) * HD;

#pragma unroll
    for (int i = 0; i < 8; i++) {
        int e = tid + i * 256;
        int r = e >> 4, c = e & 15;
        cp16(fl_addr(sQ, r, c), Qp + (size_t)r * NQ + c * 8);
    }
    fl_load_kv(sKV, sKV + 64 * 256, Kp0, Vp0, tid);
    asm volatile("cp.async.commit_group;" ::: "memory");

    float m_lo = -1e30f, m_hi = -1e30f;
    float l_lo = 0.f, l_hi = 0.f;
    float acc[16][4];
#pragma unroll
    for (int g = 0; g < 16; g++)
#pragma unroll
        for (int f = 0; f < 4; f++) acc[g][f] = 0.f;

    int m0 = warp * 16;
    int lrow = lane & 15;
    int lch  = lane >> 4;
    int rq_lo = qt0 + m0 + (lane >> 2);
    int rq_hi = rq_lo + 8;
    int cbase = (lane & 3) * 2;

    int n_kt = qt0 / 64 + 2;
    for (int kt = 0; kt < n_kt; kt++) {
        int kt0 = kt * 64;
        if (kt + 1 < n_kt) {
            uint32_t st = sKV + ((kt + 1) & 1) * (2 * 64 * 256);
            fl_load_kv(st, st + 64 * 256,
                       Kp0 + (size_t)(kt + 1) * 64 * NKVD,
                       Vp0 + (size_t)(kt + 1) * 64 * NKVD, tid);
            asm volatile("cp.async.commit_group;" ::: "memory");
            asm volatile("cp.async.wait_group 1;" ::: "memory");
        } else {
            asm volatile("cp.async.wait_group 0;" ::: "memory");
        }
        __syncthreads();

        uint32_t sK = sKV + (kt & 1) * (2 * 64 * 256);
        uint32_t sV = sK + 64 * 256;

        float sacc[8][4];
#pragma unroll
        for (int n = 0; n < 8; n++)
#pragma unroll
            for (int f = 0; f < 4; f++) sacc[n][f] = 0.f;

#pragma unroll
        for (int ks = 0; ks < 8; ks++) {
            uint32_t a[4];
            ldsm_x4(a, fl_addr(sQ, m0 + lrow, 2 * ks + lch));
#pragma unroll
            for (int g = 0; g < 4; g++) {
                uint32_t kf[4];
                ldsm_x4(kf, fl_addr(sK, g * 16 + lrow, 2 * ks + lch));
                uint32_t b0[2] = {kf[0], kf[2]};
                uint32_t b1[2] = {kf[1], kf[3]};
                mma16816(sacc[2 * g],     a, b0);
                mma16816(sacc[2 * g + 1], a, b1);
            }
        }

        if (kt >= n_kt - 2) {
#pragma unroll
            for (int n = 0; n < 8; n++) {
                int c0 = kt0 + n * 8 + cbase, c1 = c0 + 1;
                if (c0 > rq_lo) sacc[n][0] = -1e30f;
                if (c1 > rq_lo) sacc[n][1] = -1e30f;
                if (c0 > rq_hi) sacc[n][2] = -1e30f;
                if (c1 > rq_hi) sacc[n][3] = -1e30f;
            }
        }

        float mx_lo = -1e30f, mx_hi = -1e30f;
#pragma unroll
        for (int n = 0; n < 8; n++) {
            mx_lo = fmaxf(mx_lo, fmaxf(sacc[n][0], sacc[n][1]));
            mx_hi = fmaxf(mx_hi, fmaxf(sacc[n][2], sacc[n][3]));
        }
#pragma unroll
        for (int off = 1; off <= 2; off <<= 1) {
            mx_lo = fmaxf(mx_lo, __shfl_xor_sync(0xffffffffu, mx_lo, off));
            mx_hi = fmaxf(mx_hi, __shfl_xor_sync(0xffffffffu, mx_hi, off));
        }
        float mn_lo = fmaxf(m_lo, mx_lo);
        float mn_hi = fmaxf(m_hi, mx_hi);
        float sum_lo = 0.f, sum_hi = 0.f;
#pragma unroll
        for (int n = 0; n < 8; n++) {
            sacc[n][0] = exp2f(sacc[n][0] - mn_lo);
            sacc[n][1] = exp2f(sacc[n][1] - mn_lo);
            sacc[n][2] = exp2f(sacc[n][2] - mn_hi);
            sacc[n][3] = exp2f(sacc[n][3] - mn_hi);
            sum_lo += sacc[n][0] + sacc[n][1];
            sum_hi += sacc[n][2] + sacc[n][3];
        }
#pragma unroll
        for (int off = 1; off <= 2; off <<= 1) {
            sum_lo += __shfl_xor_sync(0xffffffffu, sum_lo, off);
            sum_hi += __shfl_xor_sync(0xffffffffu, sum_hi, off);
        }
        float al_lo = exp2f(m_lo - mn_lo);
        float al_hi = exp2f(m_hi - mn_hi);
        l_lo = l_lo * al_lo + sum_lo;  m_lo = mn_lo;
        l_hi = l_hi * al_hi + sum_hi;  m_hi = mn_hi;
#pragma unroll
        for (int g = 0; g < 16; g++) {
            acc[g][0] *= al_lo; acc[g][1] *= al_lo;
            acc[g][2] *= al_hi; acc[g][3] *= al_hi;
        }

        uint32_t pf[4][4];
#pragma unroll
        for (int j = 0; j < 4; j++) {
            __half2 p0 = __floats2half2_rn(sacc[2*j][0],   sacc[2*j][1]);
            __half2 p1 = __floats2half2_rn(sacc[2*j][2],   sacc[2*j][3]);
            __half2 p2 = __floats2half2_rn(sacc[2*j+1][0], sacc[2*j+1][1]);
            __half2 p3 = __floats2half2_rn(sacc[2*j+1][2], sacc[2*j+1][3]);
            pf[j][0] = *(uint32_t*)&p0;
            pf[j][1] = *(uint32_t*)&p1;
            pf[j][2] = *(uint32_t*)&p2;
            pf[j][3] = *(uint32_t*)&p3;
        }

        int vrow_off = (lane & 7) + ((lane >> 3) & 1) * 8;
#pragma unroll
        for (int j = 0; j < 4; j++) {
            int c0 = j * 16;
#pragma unroll
            for (int g = 0; g < 8; g++) {
                uint32_t vf[4];
                ldsm_x4_t(vf, fl_addr(sV, c0 + vrow_off, 2 * g + lch));
                uint32_t b0[2] = {vf[0], vf[1]};
                uint32_t b1[2] = {vf[2], vf[3]};
                mma16816(acc[2 * g],     pf[j], b0);
                mma16816(acc[2 * g + 1], pf[j], b1);
            }
        }
        __syncthreads();
    }

    float inv_lo = 1.f / l_lo, inv_hi = 1.f / l_hi;
    size_t base_lo = (size_t)(b * TT + rq_lo) * NQ + h * HD;
    size_t base_hi = (size_t)(b * TT + rq_hi) * NQ + h * HD;
#pragma unroll
    for (int g = 0; g < 16; g++) {
        int d = g * 8 + cbase;
        *(__half2*)&O[base_lo + d] = __floats2half2_rn(acc[g][0] * inv_lo, acc[g][1] * inv_lo);
        *(__half2*)&O[base_hi + d] = __floats2half2_rn(acc[g][2] * inv_hi, acc[g][3] * inv_hi);
    }
}

// ---------------- launch ----------------
extern "C" void kernel_launch(void* const* d_in, const int* in_sizes, int n_in,
                              void* d_out, int out_size)
{
    const float* x   = (const float*)d_in[0];
    const float* wq  = (const float*)d_in[1];
    const float* wk  = (const float*)d_in[2];
    const float* wv  = (const float*)d_in[3];
    const float* wo  = (const float*)d_in[4];
    const float* qnw = (const float*)d_in[5];
    const float* knw = (const float*)d_in[6];
    float* out = (float*)d_out;

    __half *x16, *wt, *wot, *a16, *q16, *k16, *v16;
    float *ctab, *stab;
    cudaGetSymbolAddress((void**)&x16, g_x16);
    cudaGetSymbolAddress((void**)&wt, g_wt);
    cudaGetSymbolAddress((void**)&wot, g_wot);
    cudaGetSymbolAddress((void**)&a16, g_attn16);
    cudaGetSymbolAddress((void**)&q16, g_q16);
    cudaGetSymbolAddress((void**)&k16, g_k16);
    cudaGetSymbolAddress((void**)&v16, g_v16);
    cudaGetSymbolAddress((void**)&ctab, g_cos);
    cudaGetSymbolAddress((void**)&stab, g_sin);

    cudaFuncSetAttribute(gemm_f16_kernel<float>,
                         cudaFuncAttributeMaxDynamicSharedMemorySize, GEMM_SMEM);
    cudaFuncSetAttribute(gemm_qkv_kernel,
                         cudaFuncAttributeMaxDynamicSharedMemorySize, GEMM_SMEM);
    cudaFuncSetAttribute(flash16_kernel,
                         cudaFuncAttributeMaxDynamicSharedMemorySize, FL_SMEM);

    // Q scale: 1/sqrt(HD) * log2(e)  -> base-2 softmax in flash
    const float qscale = 0.08838834764831845f * 1.4426950408889634f;

    // launch 0: RoPE tables (one-time fp64)
    rope_table_kernel<<<(TT * 64 + 255) / 256, 256>>>(ctab, stab);
    // launch 1: x -> fp16
    convert_f16_kernel<<<(MROWS * HID + 255) / 256, 256>>>(x, x16, MROWS * HID);
    // launch 2: wq + wk + wv transpose (merged)
    transpose_qkvw_kernel<<<dim3(NQ / 32, HID / 32, 3), dim3(32, 8)>>>(wq, wk, wv, wt);
    // launch 3: fused QKV projection + RMSNorm + RoPE / V-convert  <-- ncu capture slot
    gemm_qkv_kernel<<<dim3(NQKV / GEMM_BN, MROWS / GEMM_BM), GEMM_THREADS, GEMM_SMEM>>>(
        x16, wt, qnw, knw, ctab, stab, q16, k16, v16, qscale);
    // launch 4: wo transpose
    transpose_f16_kernel<<<dim3(HID / 32, NQ / 32), dim3(32, 8)>>>(wo, wot, NQ, HID);
    // launch 5: flash attention (base-2 softmax, LPT order)
    flash16_kernel<<<dim3(TT / FL_QM, NH, BB), 256, FL_SMEM>>>(q16, k16, v16, a16);
    // launch 6: output projection
    gemm_f16_kernel<float><<<dim3(HID / GEMM_BN, MROWS / GEMM_BM), GEMM_THREADS, GEMM_SMEM>>>(
        a16, wot, out, MROWS, HID, NQ);
}